// round 8
// baseline (speedup 1.0000x reference)
#include <cuda_runtime.h>
#include <cuda_bf16.h>
#include <math.h>
#include <stdint.h>

// ---------------- problem constants ----------------
#define BATCH   2
#define SEQLEN  2048
#define DMODEL  512
#define DSTATE  64
#define DCONV   4
#define NHEADS  16
#define HEADDIM 64
#define DINNER  1024
#define DIP     2192                   // 2*DINNER + 2*DSTATE + NHEADS
#define MROWS   (BATCH*SEQLEN)         // 4096
#define CHUNK   64
#define NCHUNK  (SEQLEN/CHUNK)         // 32
#define NCI     (BATCH*NHEADS*NCHUNK)  // 1024 chunk instances

// ---------------- scratch ----------------
__device__ float g_proj  [(size_t)MROWS * DIP];
__device__ float g_xssm  [(size_t)MROWS * DINNER];
__device__ float g_dA    [(size_t)MROWS * NHEADS];
__device__ float g_y     [(size_t)MROWS * DINNER];
__device__ float g_P     [(size_t)NCI * CHUNK];
__device__ float g_vend  [(size_t)NCI * DSTATE * HEADDIM];
__device__ float g_hstart[(size_t)NCI * DSTATE * HEADDIM];

// bf16 split tensors
__device__ __nv_bfloat16 g_xhi [(size_t)MROWS * DMODEL];
__device__ __nv_bfloat16 g_xlo [(size_t)MROWS * DMODEL];
__device__ __nv_bfloat16 g_wihi[(size_t)DIP * DMODEL];
__device__ __nv_bfloat16 g_wilo[(size_t)DIP * DMODEL];
__device__ __nv_bfloat16 g_wohi[(size_t)DMODEL * DINNER];
__device__ __nv_bfloat16 g_wolo[(size_t)DMODEL * DINNER];
__device__ __nv_bfloat16 g_yhi [(size_t)MROWS * DINNER];
__device__ __nv_bfloat16 g_ylo [(size_t)MROWS * DINNER];

// ================= helpers =================
__device__ __forceinline__ uint32_t smem_u32(const void* p) {
    uint32_t a;
    asm("{ .reg .u64 t; cvta.to.shared.u64 t, %1; cvt.u32.u64 %0, t; }"
        : "=r"(a) : "l"(p));
    return a;
}

#define LDSM4(r, addr) \
    asm volatile("ldmatrix.sync.aligned.m8n8.x4.shared.b16 {%0,%1,%2,%3}, [%4];" \
        : "=r"((r)[0]), "=r"((r)[1]), "=r"((r)[2]), "=r"((r)[3]) : "r"(addr))

#define MMA_BF16(c, a, b) \
    asm volatile("mma.sync.aligned.m16n8k16.row.col.f32.bf16.bf16.f32 " \
        "{%0,%1,%2,%3}, {%4,%5,%6,%7}, {%8,%9}, {%0,%1,%2,%3};" \
        : "+f"((c)[0]), "+f"((c)[1]), "+f"((c)[2]), "+f"((c)[3]) \
        : "r"((a)[0]), "r"((a)[1]), "r"((a)[2]), "r"((a)[3]), \
          "r"((b)[0]), "r"((b)[1]))

#define CP_ASYNC16(dst, src, sz) \
    asm volatile("cp.async.cg.shared.global [%0], [%1], 16, %2;" \
        :: "r"(dst), "l"(src), "r"(sz))
#define CP_COMMIT()  asm volatile("cp.async.commit_group;" ::: "memory")
#define CP_WAIT2()   asm volatile("cp.async.wait_group 2;" ::: "memory")
#define CP_WAIT1()   asm volatile("cp.async.wait_group 1;" ::: "memory")
#define CP_WAIT0()   asm volatile("cp.async.wait_group 0;" ::: "memory")

// ============================================================
// split: fp32 -> (hi bf16, lo bf16)
// ============================================================
__global__ void split_bf16_kernel(const float* __restrict__ s,
                                  __nv_bfloat16* __restrict__ hi,
                                  __nv_bfloat16* __restrict__ lo, int n)
{
    int i = blockIdx.x * blockDim.x + threadIdx.x;
    if (i >= n) return;
    float v = s[i];
    __nv_bfloat16 h = __float2bfloat16(v);
    hi[i] = h;
    lo[i] = __float2bfloat16(v - __bfloat162float(h));
}

// ============================================================
// bf16x3 GEMM via mma.sync, 4-stage cp.async pipeline.
//   C[M,N] = (Ahi+Alo) @ (Bhi+Blo)^T, dropping Alo*Blo.
// A:[M,K], B:[N,K] row-major bf16; C fp32 row-major ld=N.
// CTA 128x128, Kc=32, 256 threads (8 warps, 4x2), warp tile 32x64.
// 80B-padded smem rows; B frags loaded as paired ldmatrix.x4.
// grid: (ceil(N/128), M/128). M,K multiples of 128/32; N guarded (zfill).
// ============================================================
#define TILEB   10240      // 128 rows * 80B
#define STAGEB  40960      // 4 tiles
#define NSTAGE  4
#define GSMEM   (STAGEB*NSTAGE)   // 160KB

__global__ __launch_bounds__(256, 1)
void gemm_bf16x3_kernel(const __nv_bfloat16* __restrict__ Ahi_g,
                        const __nv_bfloat16* __restrict__ Alo_g,
                        const __nv_bfloat16* __restrict__ Bhi_g,
                        const __nv_bfloat16* __restrict__ Blo_g,
                        float* __restrict__ C, int N, int K)
{
    extern __shared__ char dsm[];
    const uint32_t sb = smem_u32(dsm);
    const int tid  = threadIdx.x;
    const int wid  = tid >> 5;
    const int lane = tid & 31;
    const int wm   = wid & 3;          // 0..3 -> 32-row slice
    const int wn   = wid >> 2;         // 0..1 -> 64-col slice
    const int m0 = blockIdx.y * 128;
    const int n0 = blockIdx.x * 128;

    // ---- async stage loader: 4 tiles x 128 rows x 32 bf16 ----
    auto stage_load = [&](int kc, int buf) {
        #pragma unroll
        for (int i = 0; i < 8; i++) {
            const int u   = tid + i * 256;
            const int t   = u >> 9;          // tile 0..3
            const int v   = u & 511;
            const int row = v >> 2;
            const int seg = v & 3;
            const uint32_t dst = sb + buf*STAGEB + t*TILEB + row*80 + seg*16;
            const __nv_bfloat16* src;
            int gr; int sz = 16;
            if (t < 2) { src = (t == 0) ? Ahi_g : Alo_g; gr = m0 + row; }
            else {
                src = (t == 2) ? Bhi_g : Blo_g; gr = n0 + row;
                if (gr >= N) { gr = 0; sz = 0; }
            }
            const void* g = src + (size_t)gr * K + kc*32 + seg*8;
            CP_ASYNC16(dst, g, sz);
        }
        CP_COMMIT();
    };

    float acc[2][8][4];
    #pragma unroll
    for (int mt = 0; mt < 2; mt++)
        #pragma unroll
        for (int nt = 0; nt < 8; nt++)
            #pragma unroll
            for (int q = 0; q < 4; q++) acc[mt][nt][q] = 0.f;

    const int nk = K >> 5;
    // prologue: fill 3 stages
    stage_load(0, 0);
    if (nk > 1) stage_load(1, 1);
    if (nk > 2) stage_load(2, 2);

    for (int kc = 0; kc < nk; kc++) {
        const int rem = nk - 1 - kc;        // stages still needed after kc
        if (rem >= 2)      CP_WAIT2();
        else if (rem == 1) CP_WAIT1();
        else               CP_WAIT0();
        __syncthreads();

        if (kc + 3 < nk) stage_load(kc + 3, (kc + 3) & 3);

        const uint32_t base = sb + (kc & 3) * STAGEB;

        #pragma unroll
        for (int ks = 0; ks < 2; ks++) {
            // A fragments: hi & lo, 2 m-tiles each (ldmatrix.x4 = m16k16)
            uint32_t ah[2][4], al[2][4];
            #pragma unroll
            for (int mt = 0; mt < 2; mt++) {
                const uint32_t ra = base
                    + (wm*32 + mt*16 + (lane & 15)) * 80
                    + ks*32 + ((lane >> 4) & 1) * 16;
                LDSM4(ah[mt], ra);
                LDSM4(al[mt], ra + TILEB);
            }
            // B fragments: pairs of nt per ldmatrix.x4
            uint32_t bh[8][2], bl[8][2];
            #pragma unroll
            for (int np = 0; np < 4; np++) {
                const uint32_t rb = base + 2*TILEB
                    + (wn*64 + np*16 + ((lane >> 4) & 1) * 8 + (lane & 7)) * 80
                    + ks*32 + ((lane >> 3) & 1) * 16;
                uint32_t r4[4];
                LDSM4(r4, rb);
                bh[np*2][0] = r4[0]; bh[np*2][1] = r4[1];
                bh[np*2+1][0] = r4[2]; bh[np*2+1][1] = r4[3];
                LDSM4(r4, rb + TILEB);
                bl[np*2][0] = r4[0]; bl[np*2][1] = r4[1];
                bl[np*2+1][0] = r4[2]; bl[np*2+1][1] = r4[3];
            }
            #pragma unroll
            for (int mt = 0; mt < 2; mt++)
                #pragma unroll
                for (int nt = 0; nt < 8; nt++) {
                    MMA_BF16(acc[mt][nt], ah[mt], bh[nt]);
                    MMA_BF16(acc[mt][nt], ah[mt], bl[nt]);
                    MMA_BF16(acc[mt][nt], al[mt], bh[nt]);
                }
        }
        __syncthreads();
    }

    // ---- epilogue ----
    #pragma unroll
    for (int mt = 0; mt < 2; mt++) {
        const int r0 = m0 + wm*32 + mt*16 + (lane >> 2);
        #pragma unroll
        for (int nt = 0; nt < 8; nt++) {
            const int cc = n0 + wn*64 + nt*8 + (lane & 3)*2;
            if (cc < N) {
                *(float2*)(C + (size_t)r0       * N + cc) =
                    make_float2(acc[mt][nt][0], acc[mt][nt][1]);
                *(float2*)(C + (size_t)(r0 + 8) * N + cc) =
                    make_float2(acc[mt][nt][2], acc[mt][nt][3]);
            }
        }
    }
}

// ============================================================
// depthwise causal conv1d + bias + SiLU -> g_xssm
// ============================================================
__global__ void conv_silu_kernel(const float* __restrict__ cw,
                                 const float* __restrict__ cb)
{
    int idx = blockIdx.x * blockDim.x + threadIdx.x;
    if (idx >= BATCH * SEQLEN * DINNER) return;
    const int c = idx % DINNER;
    const int t = (idx / DINNER) % SEQLEN;
    const int b = idx / (DINNER * SEQLEN);

    const float* base = g_proj + (size_t)b * SEQLEN * DIP + DINNER + c;
    float acc = cb[c];
    #pragma unroll
    for (int j = 0; j < DCONV; j++) {
        const int ts = t - (DCONV - 1) + j;
        if (ts >= 0) acc = fmaf(cw[c*DCONV + j], base[(size_t)ts * DIP], acc);
    }
    g_xssm[idx] = acc / (1.f + expf(-acc));
}

// ============================================================
// dt path: dA = exp(softplus(dt_raw + dt_bias) * (-exp(A_log)))
// ============================================================
__global__ void dt_kernel(const float* __restrict__ A_log,
                          const float* __restrict__ dt_bias)
{
    int idx = blockIdx.x * blockDim.x + threadIdx.x;
    if (idx >= BATCH * SEQLEN * NHEADS) return;
    const int h = idx % NHEADS;
    const int row = idx / NHEADS;

    float dtr = g_proj[(size_t)row * DIP + 2*DINNER + 2*DSTATE + h] + dt_bias[h];
    float sp = (dtr > 20.f) ? dtr : log1pf(expf(dtr));
    float Aneg = -expf(A_log[h]);
    g_dA[idx] = expf(sp * Aneg);
}

// ============================================================
// Phase A: per-chunk local scan (zero init). B/C staged in 32-row
// halves to cut smem (raises blocks/SM).
// ============================================================
__global__ __launch_bounds__(128, 7)
void scan_chunk_kernel()
{
    const int pg = blockIdx.x;
    const int h  = blockIdx.y;
    const int bz = blockIdx.z;
    const int b  = bz >> 5;
    const int c  = bz & 31;

    const int tid  = threadIdx.x;
    const int lane = tid & 31;
    const int w    = tid >> 5;
    const int pi   = lane & 3;
    const int ng   = lane >> 2;
    const int p_local = w*4 + pi;
    const int n0   = ng * 8;

    __shared__ float sB [32][68];
    __shared__ float sC [32][68];
    __shared__ float sX [64][16];
    __shared__ float sDA[64];
    __shared__ float sP [64];

    const size_t rowbase = (size_t)b * SEQLEN + (size_t)c * CHUNK;
    const int pcol = h*64 + pg*16;
    const size_t ci = ((size_t)(b*NHEADS + h) * NCHUNK + c);

    // stage x, dA (full chunk)
    for (int u = tid; u < 64*4; u += 128) {
        const int r  = u >> 2;
        const int c4 = (u & 3) * 4;
        *(float4*)&sX[r][c4] =
            *(const float4*)(g_xssm + (rowbase + r) * (size_t)DINNER + pcol + c4);
    }
    if (tid < 64) {
        float v = g_dA[(rowbase + tid) * NHEADS + h];
        sDA[tid] = v;
        sP[tid]  = v;
    }
    __syncthreads();

    // inclusive cumprod of dA
    #pragma unroll
    for (int off = 1; off < 64; off <<= 1) {
        float v = 0.f;
        if (tid < 64) {
            v = sP[tid];
            if (tid >= off) v *= sP[tid - off];
        }
        __syncthreads();
        if (tid < 64) sP[tid] = v;
        __syncthreads();
    }
    if (tid < 64 && pg == 0)
        g_P[ci*CHUNK + tid] = sP[tid];

    float s[8];
    #pragma unroll
    for (int j = 0; j < 8; j++) s[j] = 0.f;

    #pragma unroll 1
    for (int half = 0; half < 2; half++) {
        __syncthreads();
        // stage B, C rows [half*32, half*32+32)
        for (int u = tid; u < 32*16; u += 128) {
            const int r  = u >> 4;
            const int c4 = (u & 15) * 4;
            const float* src = g_proj + (rowbase + half*32 + r) * (size_t)DIP;
            *(float4*)&sB[r][c4] = *(const float4*)(src + 2*DINNER + c4);
            *(float4*)&sC[r][c4] = *(const float4*)(src + 2*DINNER + DSTATE + c4);
        }
        __syncthreads();

        #pragma unroll 1
        for (int g = 0; g < 32; g += 8) {
            float acc[8];
            #pragma unroll
            for (int q = 0; q < 8; q++) {
                const int tt = g + q;                 // local row in half
                const int gt = half*32 + tt;          // global step in chunk
                const float da = sDA[gt];
                const float xv = sX[gt][p_local];
                float4 b0 = *(const float4*)&sB[tt][n0];
                float4 b1 = *(const float4*)&sB[tt][n0+4];
                float4 c0 = *(const float4*)&sC[tt][n0];
                float4 c1 = *(const float4*)&sC[tt][n0+4];
                s[0] = fmaf(da, s[0], b0.x * xv);
                s[1] = fmaf(da, s[1], b0.y * xv);
                s[2] = fmaf(da, s[2], b0.z * xv);
                s[3] = fmaf(da, s[3], b0.w * xv);
                s[4] = fmaf(da, s[4], b1.x * xv);
                s[5] = fmaf(da, s[5], b1.y * xv);
                s[6] = fmaf(da, s[6], b1.z * xv);
                s[7] = fmaf(da, s[7], b1.w * xv);
                float a0 = c0.x * s[0];
                float a1 = c0.y * s[1];
                a0 = fmaf(c0.z, s[2], a0);
                a1 = fmaf(c0.w, s[3], a1);
                a0 = fmaf(c1.x, s[4], a0);
                a1 = fmaf(c1.y, s[5], a1);
                a0 = fmaf(c1.z, s[6], a0);
                a1 = fmaf(c1.w, s[7], a1);
                acc[q] = a0 + a1;
            }
            #pragma unroll
            for (int q = 0; q < 8; q++) {
                float a = acc[q];
                a += __shfl_xor_sync(0xffffffffu, a, 4);
                a += __shfl_xor_sync(0xffffffffu, a, 8);
                a += __shfl_xor_sync(0xffffffffu, a, 16);
                acc[q] = a;
            }
            if (ng == 0) {
                #pragma unroll
                for (int q = 0; q < 8; q++) {
                    g_y[(rowbase + half*32 + g + q) * (size_t)DINNER + pcol + p_local]
                        = acc[q];
                }
            }
        }
    }

    float* vend = g_vend + ci * (size_t)(DSTATE*HEADDIM);
    #pragma unroll
    for (int j = 0; j < 8; j++)
        vend[(n0 + j) * HEADDIM + pg*16 + p_local] = s[j];
}

// ============================================================
// Phase B: carry propagation across chunks.
// ============================================================
__global__ __launch_bounds__(256, 1)
void carry_kernel()
{
    const int bh  = blockIdx.x;
    const int tid = threadIdx.x;

    float hreg[16];
    #pragma unroll
    for (int k = 0; k < 16; k++) hreg[k] = 0.f;

    for (int c = 0; c < NCHUNK; c++) {
        const size_t ci = (size_t)bh * NCHUNK + c;
        const float Pend = g_P[ci*CHUNK + (CHUNK-1)];
        float*       hs = g_hstart + ci * (size_t)(DSTATE*HEADDIM);
        const float* ve = g_vend   + ci * (size_t)(DSTATE*HEADDIM);
        #pragma unroll
        for (int k = 0; k < 16; k++) {
            const int cell = tid + k*256;
            hs[cell] = hreg[k];
            hreg[k] = fmaf(Pend, hreg[k], ve[cell]);
        }
    }
}

// ============================================================
// Phase C: correction + gate, writes y as bf16 hi/lo split.
// ============================================================
__global__ __launch_bounds__(256, 4)
void correct_gate_kernel()
{
    const int ci = blockIdx.x;
    const int c  = ci & 31;
    const int bh = ci >> 5;
    const int h  = bh & 15;
    const int b  = bh >> 4;
    const int tid = threadIdx.x;

    __shared__ float sCt[64][72];
    __shared__ float sHS[64][64];
    __shared__ float sPc[64];

    const size_t rowbase = (size_t)b * SEQLEN + (size_t)c * CHUNK;

    for (int u = tid; u < 64*16; u += 256) {
        const int r  = u >> 4;
        const int c4 = (u & 15) * 4;
        float4 v = *(const float4*)(g_proj + (rowbase + r) * (size_t)DIP
                                    + 2*DINNER + DSTATE + c4);
        sCt[c4+0][r] = v.x; sCt[c4+1][r] = v.y;
        sCt[c4+2][r] = v.z; sCt[c4+3][r] = v.w;
    }
    const float* hs = g_hstart + (size_t)ci * (DSTATE*HEADDIM);
    for (int u = tid; u < 64*16; u += 256) {
        const int r  = u >> 4;
        const int c4 = (u & 15) * 4;
        *(float4*)&sHS[r][c4] = *(const float4*)(hs + r*HEADDIM + c4);
    }
    if (tid < 64) sPc[tid] = g_P[(size_t)ci*CHUNK + tid];
    __syncthreads();

    const int tx = tid & 15;
    const int ty = tid >> 4;
    const int t0 = ty * 4;
    const int p0 = tx * 4;

    float acc[4][4];
    #pragma unroll
    for (int i = 0; i < 4; i++)
        #pragma unroll
        for (int j = 0; j < 4; j++) acc[i][j] = 0.f;

    #pragma unroll 4
    for (int n = 0; n < 64; n++) {
        float4 cv = *(const float4*)&sCt[n][t0];
        float4 hv = *(const float4*)&sHS[n][p0];
        float ct[4] = {cv.x, cv.y, cv.z, cv.w};
        float hh[4] = {hv.x, hv.y, hv.z, hv.w};
        #pragma unroll
        for (int i = 0; i < 4; i++)
            #pragma unroll
            for (int j = 0; j < 4; j++)
                acc[i][j] = fmaf(ct[i], hh[j], acc[i][j]);
    }

    #pragma unroll
    for (int i = 0; i < 4; i++) {
        const size_t row = rowbase + t0 + i;
        const float P = sPc[t0 + i];
        float4 yp = *(const float4*)(g_y + row * (size_t)DINNER + h*64 + p0);
        float4 zv = *(const float4*)(g_proj + row * (size_t)DIP + h*64 + p0);
        float ov[4];
        ov[0] = (yp.x + P*acc[i][0]) * (zv.x / (1.f + expf(-zv.x)));
        ov[1] = (yp.y + P*acc[i][1]) * (zv.y / (1.f + expf(-zv.y)));
        ov[2] = (yp.z + P*acc[i][2]) * (zv.z / (1.f + expf(-zv.z)));
        ov[3] = (yp.w + P*acc[i][3]) * (zv.w / (1.f + expf(-zv.w)));
        const size_t yo = row * (size_t)DINNER + h*64 + p0;
        #pragma unroll
        for (int j = 0; j < 4; j++) {
            __nv_bfloat16 hv = __float2bfloat16(ov[j]);
            g_yhi[yo + j] = hv;
            g_ylo[yo + j] = __float2bfloat16(ov[j] - __bfloat162float(hv));
        }
    }
}

// ============================================================
// launch
// ============================================================
extern "C" void kernel_launch(void* const* d_in, const int* in_sizes, int n_in,
                              void* d_out, int out_size)
{
    const float* x       = (const float*)d_in[0];
    const float* W_in    = (const float*)d_in[1];
    const float* conv_w  = (const float*)d_in[2];
    const float* conv_b  = (const float*)d_in[3];
    const float* A_log   = (const float*)d_in[4];
    const float* dt_bias = (const float*)d_in[5];
    const float* W_out   = (const float*)d_in[6];
    float* out = (float*)d_out;

    float* proj; cudaGetSymbolAddress((void**)&proj, g_proj);
    __nv_bfloat16 *xhi, *xlo, *wihi, *wilo, *wohi, *wolo, *yhi, *ylo;
    cudaGetSymbolAddress((void**)&xhi,  g_xhi);
    cudaGetSymbolAddress((void**)&xlo,  g_xlo);
    cudaGetSymbolAddress((void**)&wihi, g_wihi);
    cudaGetSymbolAddress((void**)&wilo, g_wilo);
    cudaGetSymbolAddress((void**)&wohi, g_wohi);
    cudaGetSymbolAddress((void**)&wolo, g_wolo);
    cudaGetSymbolAddress((void**)&yhi,  g_yhi);
    cudaGetSymbolAddress((void**)&ylo,  g_ylo);

    cudaFuncSetAttribute(gemm_bf16x3_kernel,
                         cudaFuncAttributeMaxDynamicSharedMemorySize, GSMEM);

    // 0) split inputs / weights into bf16 hi/lo
    {
        int n1 = MROWS * DMODEL;
        split_bf16_kernel<<<(n1 + 255)/256, 256>>>(x, xhi, xlo, n1);
        int n2 = DIP * DMODEL;
        split_bf16_kernel<<<(n2 + 255)/256, 256>>>(W_in, wihi, wilo, n2);
        int n3 = DMODEL * DINNER;
        split_bf16_kernel<<<(n3 + 255)/256, 256>>>(W_out, wohi, wolo, n3);
    }
    // 1) in_proj (HMMA): proj = x @ W_in^T   M=4096, N=2192, K=512
    {
        dim3 grid((DIP + 127)/128, MROWS/128);
        gemm_bf16x3_kernel<<<grid, 256, GSMEM>>>(xhi, xlo, wihi, wilo,
                                                 proj, DIP, DMODEL);
    }
    // 2) conv + silu
    {
        int total = BATCH*SEQLEN*DINNER;
        conv_silu_kernel<<<(total + 255)/256, 256>>>(conv_w, conv_b);
    }
    // 3) dt -> dA
    {
        int total = BATCH*SEQLEN*NHEADS;
        dt_kernel<<<(total + 255)/256, 256>>>(A_log, dt_bias);
    }
    // 4a) per-chunk local scan
    {
        dim3 grid(4, NHEADS, BATCH*NCHUNK);
        scan_chunk_kernel<<<grid, 128>>>();
    }
    // 4b) carry propagation
    carry_kernel<<<BATCH*NHEADS, 256>>>();
    // 4c) correction + gate (writes y hi/lo bf16)
    correct_gate_kernel<<<NCI, 256>>>();
    // 5) out_proj (HMMA): out = y @ W_out^T  M=4096, N=512, K=1024
    {
        dim3 grid(DMODEL/128, MROWS/128);
        gemm_bf16x3_kernel<<<grid, 256, GSMEM>>>(yhi, ylo, wohi, wolo,
                                                 out, DMODEL, DINNER);
    }
}

// round 10
// speedup vs baseline: 1.5415x; 1.5415x over previous
#include <cuda_runtime.h>
#include <cuda_bf16.h>
#include <math.h>
#include <stdint.h>

// ---------------- problem constants ----------------
#define BATCH   2
#define SEQLEN  2048
#define DMODEL  512
#define DSTATE  64
#define DCONV   4
#define NHEADS  16
#define HEADDIM 64
#define DINNER  1024
#define DIP     2192                   // 2*DINNER + 2*DSTATE + NHEADS
#define MROWS   (BATCH*SEQLEN)         // 4096
#define CHUNK   64
#define NCHUNK  (SEQLEN/CHUNK)         // 32
#define NCI     (BATCH*NHEADS*NCHUNK)  // 1024 chunk instances

// ---------------- scratch ----------------
__device__ float g_proj  [(size_t)MROWS * DIP];
__device__ float g_xssm  [(size_t)MROWS * DINNER];
__device__ float g_dA    [(size_t)MROWS * NHEADS];
__device__ float g_y     [(size_t)MROWS * DINNER];
__device__ float g_P     [(size_t)NCI * CHUNK];
__device__ float g_vend  [(size_t)NCI * DSTATE * HEADDIM];
__device__ float g_hstart[(size_t)NCI * DSTATE * HEADDIM];

// bf16 split tensors
__device__ __nv_bfloat16 g_xhi [(size_t)MROWS * DMODEL];
__device__ __nv_bfloat16 g_xlo [(size_t)MROWS * DMODEL];
__device__ __nv_bfloat16 g_wihi[(size_t)DIP * DMODEL];
__device__ __nv_bfloat16 g_wilo[(size_t)DIP * DMODEL];
__device__ __nv_bfloat16 g_wohi[(size_t)DMODEL * DINNER];
__device__ __nv_bfloat16 g_wolo[(size_t)DMODEL * DINNER];
__device__ __nv_bfloat16 g_yhi [(size_t)MROWS * DINNER];
__device__ __nv_bfloat16 g_ylo [(size_t)MROWS * DINNER];

// ================= helpers =================
__device__ __forceinline__ uint32_t smem_u32(const void* p) {
    uint32_t a;
    asm("{ .reg .u64 t; cvta.to.shared.u64 t, %1; cvt.u32.u64 %0, t; }"
        : "=r"(a) : "l"(p));
    return a;
}

#define LDSM4(r, addr) \
    asm volatile("ldmatrix.sync.aligned.m8n8.x4.shared.b16 {%0,%1,%2,%3}, [%4];" \
        : "=r"((r)[0]), "=r"((r)[1]), "=r"((r)[2]), "=r"((r)[3]) : "r"(addr))

#define MMA_BF16(c, a, b) \
    asm volatile("mma.sync.aligned.m16n8k16.row.col.f32.bf16.bf16.f32 " \
        "{%0,%1,%2,%3}, {%4,%5,%6,%7}, {%8,%9}, {%0,%1,%2,%3};" \
        : "+f"((c)[0]), "+f"((c)[1]), "+f"((c)[2]), "+f"((c)[3]) \
        : "r"((a)[0]), "r"((a)[1]), "r"((a)[2]), "r"((a)[3]), \
          "r"((b)[0]), "r"((b)[1]))

#define CP_ASYNC16(dst, src, sz) \
    asm volatile("cp.async.cg.shared.global [%0], [%1], 16, %2;" \
        :: "r"(dst), "l"(src), "r"(sz))
#define CP_COMMIT()  asm volatile("cp.async.commit_group;" ::: "memory")
#define CP_WAIT1()   asm volatile("cp.async.wait_group 1;" ::: "memory")
#define CP_WAIT0()   asm volatile("cp.async.wait_group 0;" ::: "memory")

// ============================================================
// split: fp32 -> (hi bf16, lo bf16)
// ============================================================
__global__ void split_bf16_kernel(const float* __restrict__ s,
                                  __nv_bfloat16* __restrict__ hi,
                                  __nv_bfloat16* __restrict__ lo, int n)
{
    int i = blockIdx.x * blockDim.x + threadIdx.x;
    if (i >= n) return;
    float v = s[i];
    __nv_bfloat16 h = __float2bfloat16(v);
    hi[i] = h;
    lo[i] = __float2bfloat16(v - __bfloat162float(h));
}

// ============================================================
// bf16x3 GEMM via mma.sync, 3-stage cp.async, 2 CTAs/SM.
//   C[M,N] = (Ahi+Alo) @ (Bhi+Blo)^T, dropping Alo*Blo.
// A:[M,K], B:[N,K] row-major bf16; C fp32 row-major ld=N.
// CTA 128x64, Kc=32, 256 threads (8 warps, 4x2), warp tile 32x32.
// 80B-padded smem rows. grid: (ceil(N/64), M/128). N guarded (zfill).
// ============================================================
#define ATILEB  10240      // 128 rows * 80B
#define BTILEB  5120       // 64 rows * 80B
#define STAGEB  30720      // Ahi+Alo+Bhi+Blo
#define NSTAGE  3
#define GSMEM   (STAGEB*NSTAGE)   // 92160

__global__ __launch_bounds__(256, 2)
void gemm_bf16x3_kernel(const __nv_bfloat16* __restrict__ Ahi_g,
                        const __nv_bfloat16* __restrict__ Alo_g,
                        const __nv_bfloat16* __restrict__ Bhi_g,
                        const __nv_bfloat16* __restrict__ Blo_g,
                        float* __restrict__ C, int N, int K)
{
    extern __shared__ char dsm[];
    const uint32_t sb = smem_u32(dsm);
    const int tid  = threadIdx.x;
    const int wid  = tid >> 5;
    const int lane = tid & 31;
    const int wm   = wid & 3;          // 0..3 -> 32-row slice
    const int wn   = wid >> 2;         // 0..1 -> 32-col slice
    const int m0 = blockIdx.y * 128;
    const int n0 = blockIdx.x * 64;

    // ---- async stage loader: A 2x128 rows, B 2x64 rows, 32 bf16 each ----
    auto stage_load = [&](int kc, int buf) {
        const uint32_t sbb = sb + buf * STAGEB;
        #pragma unroll
        for (int i = 0; i < 6; i++) {
            const int u = tid + i * 256;
            uint32_t dst;
            const __nv_bfloat16* src;
            int gr, row, seg, sz = 16;
            if (u < 1024) {               // A tiles
                const int t = u >> 9;     // 0=hi 1=lo
                const int v = u & 511;
                row = v >> 2; seg = v & 3;
                dst = sbb + t * ATILEB + row * 80 + seg * 16;
                src = t ? Alo_g : Ahi_g;
                gr = m0 + row;
            } else {                      // B tiles
                const int v = u - 1024;
                const int t = v >> 8;     // 0=hi 1=lo
                const int w2 = v & 255;
                row = w2 >> 2; seg = w2 & 3;
                dst = sbb + 2 * ATILEB + t * BTILEB + row * 80 + seg * 16;
                src = t ? Blo_g : Bhi_g;
                gr = n0 + row;
                if (gr >= N) { gr = 0; sz = 0; }
            }
            const void* g = src + (size_t)gr * K + kc * 32 + seg * 8;
            CP_ASYNC16(dst, g, sz);
        }
        CP_COMMIT();
    };

    float acc[2][4][4];
    #pragma unroll
    for (int mt = 0; mt < 2; mt++)
        #pragma unroll
        for (int nt = 0; nt < 4; nt++)
            #pragma unroll
            for (int q = 0; q < 4; q++) acc[mt][nt][q] = 0.f;

    const int nk = K >> 5;
    stage_load(0, 0);
    if (nk > 1) stage_load(1, 1);

    for (int kc = 0; kc < nk; kc++) {
        if (kc < nk - 1) CP_WAIT1(); else CP_WAIT0();
        __syncthreads();
        if (kc + 2 < nk) {
            int nb = kc + 2;
            stage_load(nb, nb - (nb / 3) * 3);
        }

        const uint32_t base = sb + (kc - (kc / 3) * 3) * STAGEB;

        #pragma unroll
        for (int ks = 0; ks < 2; ks++) {
            uint32_t ah[2][4], al[2][4];
            #pragma unroll
            for (int mt = 0; mt < 2; mt++) {
                const uint32_t ra = base
                    + (wm*32 + mt*16 + (lane & 15)) * 80
                    + ks*32 + ((lane >> 4) & 1) * 16;
                LDSM4(ah[mt], ra);
                LDSM4(al[mt], ra + ATILEB);
            }
            uint32_t bh[4][2], bl[4][2];
            #pragma unroll
            for (int np = 0; np < 2; np++) {
                const uint32_t rb = base + 2*ATILEB
                    + (wn*32 + np*16 + ((lane >> 4) & 1) * 8 + (lane & 7)) * 80
                    + ks*32 + ((lane >> 3) & 1) * 16;
                uint32_t r4[4];
                LDSM4(r4, rb);
                bh[np*2][0] = r4[0]; bh[np*2][1] = r4[1];
                bh[np*2+1][0] = r4[2]; bh[np*2+1][1] = r4[3];
                LDSM4(r4, rb + BTILEB);
                bl[np*2][0] = r4[0]; bl[np*2][1] = r4[1];
                bl[np*2+1][0] = r4[2]; bl[np*2+1][1] = r4[3];
            }
            #pragma unroll
            for (int mt = 0; mt < 2; mt++)
                #pragma unroll
                for (int nt = 0; nt < 4; nt++) {
                    MMA_BF16(acc[mt][nt], ah[mt], bh[nt]);
                    MMA_BF16(acc[mt][nt], ah[mt], bl[nt]);
                    MMA_BF16(acc[mt][nt], al[mt], bh[nt]);
                }
        }
    }

    // ---- epilogue ----
    #pragma unroll
    for (int mt = 0; mt < 2; mt++) {
        const int r0 = m0 + wm*32 + mt*16 + (lane >> 2);
        #pragma unroll
        for (int nt = 0; nt < 4; nt++) {
            const int cc = n0 + wn*32 + nt*8 + (lane & 3)*2;
            if (cc < N) {
                *(float2*)(C + (size_t)r0       * N + cc) =
                    make_float2(acc[mt][nt][0], acc[mt][nt][1]);
                *(float2*)(C + (size_t)(r0 + 8) * N + cc) =
                    make_float2(acc[mt][nt][2], acc[mt][nt][3]);
            }
        }
    }
}

// ============================================================
// depthwise causal conv1d + bias + SiLU -> g_xssm
// ============================================================
__global__ void conv_silu_kernel(const float* __restrict__ cw,
                                 const float* __restrict__ cb)
{
    int idx = blockIdx.x * blockDim.x + threadIdx.x;
    if (idx >= BATCH * SEQLEN * DINNER) return;
    const int c = idx % DINNER;
    const int t = (idx / DINNER) % SEQLEN;
    const int b = idx / (DINNER * SEQLEN);

    const float* base = g_proj + (size_t)b * SEQLEN * DIP + DINNER + c;
    float acc = cb[c];
    #pragma unroll
    for (int j = 0; j < DCONV; j++) {
        const int ts = t - (DCONV - 1) + j;
        if (ts >= 0) acc = fmaf(cw[c*DCONV + j], base[(size_t)ts * DIP], acc);
    }
    g_xssm[idx] = acc / (1.f + expf(-acc));
}

// ============================================================
// dt path: dA = exp(softplus(dt_raw + dt_bias) * (-exp(A_log)))
// ============================================================
__global__ void dt_kernel(const float* __restrict__ A_log,
                          const float* __restrict__ dt_bias)
{
    int idx = blockIdx.x * blockDim.x + threadIdx.x;
    if (idx >= BATCH * SEQLEN * NHEADS) return;
    const int h = idx % NHEADS;
    const int row = idx / NHEADS;

    float dtr = g_proj[(size_t)row * DIP + 2*DINNER + 2*DSTATE + h] + dt_bias[h];
    float sp = (dtr > 20.f) ? dtr : log1pf(expf(dtr));
    float Aneg = -expf(A_log[h]);
    g_dA[idx] = expf(sp * Aneg);
}

// ============================================================
// Phase A: per-chunk local scan (zero init).  (R7 version)
// ============================================================
__global__ __launch_bounds__(128, 1)
void scan_chunk_kernel()
{
    const int pg = blockIdx.x;
    const int h  = blockIdx.y;
    const int bz = blockIdx.z;
    const int b  = bz >> 5;
    const int c  = bz & 31;

    const int tid  = threadIdx.x;
    const int lane = tid & 31;
    const int w    = tid >> 5;
    const int pi   = lane & 3;
    const int ng   = lane >> 2;
    const int p_local = w*4 + pi;
    const int n0   = ng * 8;

    __shared__ float sB [64][64];
    __shared__ float sC [64][64];
    __shared__ float sX [64][16];
    __shared__ float sDA[64];
    __shared__ float sP [64];

    const size_t rowbase = (size_t)b * SEQLEN + (size_t)c * CHUNK;
    const int pcol = h*64 + pg*16;
    const size_t ci = ((size_t)(b*NHEADS + h) * NCHUNK + c);

    for (int u = tid; u < 64*16; u += 128) {
        const int r  = u >> 4;
        const int c4 = (u & 15) * 4;
        const float* src = g_proj + (rowbase + r) * (size_t)DIP;
        *(float4*)&sB[r][c4] = *(const float4*)(src + 2*DINNER + c4);
        *(float4*)&sC[r][c4] = *(const float4*)(src + 2*DINNER + DSTATE + c4);
    }
    for (int u = tid; u < 64*4; u += 128) {
        const int r  = u >> 2;
        const int c4 = (u & 3) * 4;
        *(float4*)&sX[r][c4] =
            *(const float4*)(g_xssm + (rowbase + r) * (size_t)DINNER + pcol + c4);
    }
    if (tid < 64) {
        float v = g_dA[(rowbase + tid) * NHEADS + h];
        sDA[tid] = v;
        sP[tid]  = v;
    }
    __syncthreads();

    #pragma unroll
    for (int off = 1; off < 64; off <<= 1) {
        float v = 0.f;
        if (tid < 64) {
            v = sP[tid];
            if (tid >= off) v *= sP[tid - off];
        }
        __syncthreads();
        if (tid < 64) sP[tid] = v;
        __syncthreads();
    }
    if (tid < 64 && pg == 0)
        g_P[ci*CHUNK + tid] = sP[tid];

    float s[8];
    #pragma unroll
    for (int j = 0; j < 8; j++) s[j] = 0.f;

    #pragma unroll 1
    for (int g = 0; g < 64; g += 8) {
        float acc[8];
        #pragma unroll
        for (int q = 0; q < 8; q++) {
            const int tt = g + q;
            const float da = sDA[tt];
            const float xv = sX[tt][p_local];
            float4 b0 = *(const float4*)&sB[tt][n0];
            float4 b1 = *(const float4*)&sB[tt][n0+4];
            float4 c0 = *(const float4*)&sC[tt][n0];
            float4 c1 = *(const float4*)&sC[tt][n0+4];
            s[0] = fmaf(da, s[0], b0.x * xv);
            s[1] = fmaf(da, s[1], b0.y * xv);
            s[2] = fmaf(da, s[2], b0.z * xv);
            s[3] = fmaf(da, s[3], b0.w * xv);
            s[4] = fmaf(da, s[4], b1.x * xv);
            s[5] = fmaf(da, s[5], b1.y * xv);
            s[6] = fmaf(da, s[6], b1.z * xv);
            s[7] = fmaf(da, s[7], b1.w * xv);
            float a0 = c0.x * s[0];
            float a1 = c0.y * s[1];
            a0 = fmaf(c0.z, s[2], a0);
            a1 = fmaf(c0.w, s[3], a1);
            a0 = fmaf(c1.x, s[4], a0);
            a1 = fmaf(c1.y, s[5], a1);
            a0 = fmaf(c1.z, s[6], a0);
            a1 = fmaf(c1.w, s[7], a1);
            acc[q] = a0 + a1;
        }
        #pragma unroll
        for (int q = 0; q < 8; q++) {
            float a = acc[q];
            a += __shfl_xor_sync(0xffffffffu, a, 4);
            a += __shfl_xor_sync(0xffffffffu, a, 8);
            a += __shfl_xor_sync(0xffffffffu, a, 16);
            acc[q] = a;
        }
        if (ng == 0) {
            #pragma unroll
            for (int q = 0; q < 8; q++) {
                g_y[(rowbase + g + q) * (size_t)DINNER + pcol + p_local] = acc[q];
            }
        }
    }

    float* vend = g_vend + ci * (size_t)(DSTATE*HEADDIM);
    #pragma unroll
    for (int j = 0; j < 8; j++)
        vend[(n0 + j) * HEADDIM + pg*16 + p_local] = s[j];
}

// ============================================================
// Phase B: carry propagation across chunks.
// ============================================================
__global__ __launch_bounds__(256, 1)
void carry_kernel()
{
    const int bh  = blockIdx.x;
    const int tid = threadIdx.x;

    float hreg[16];
    #pragma unroll
    for (int k = 0; k < 16; k++) hreg[k] = 0.f;

    for (int c = 0; c < NCHUNK; c++) {
        const size_t ci = (size_t)bh * NCHUNK + c;
        const float Pend = g_P[ci*CHUNK + (CHUNK-1)];
        float*       hs = g_hstart + ci * (size_t)(DSTATE*HEADDIM);
        const float* ve = g_vend   + ci * (size_t)(DSTATE*HEADDIM);
        #pragma unroll
        for (int k = 0; k < 16; k++) {
            const int cell = tid + k*256;
            hs[cell] = hreg[k];
            hreg[k] = fmaf(Pend, hreg[k], ve[cell]);
        }
    }
}

// ============================================================
// Phase C: correction + gate, writes y as bf16 hi/lo split.
// ============================================================
__global__ __launch_bounds__(256, 4)
void correct_gate_kernel()
{
    const int ci = blockIdx.x;
    const int c  = ci & 31;
    const int bh = ci >> 5;
    const int h  = bh & 15;
    const int b  = bh >> 4;
    const int tid = threadIdx.x;

    __shared__ float sCt[64][72];
    __shared__ float sHS[64][64];
    __shared__ float sPc[64];

    const size_t rowbase = (size_t)b * SEQLEN + (size_t)c * CHUNK;

    for (int u = tid; u < 64*16; u += 256) {
        const int r  = u >> 4;
        const int c4 = (u & 15) * 4;
        float4 v = *(const float4*)(g_proj + (rowbase + r) * (size_t)DIP
                                    + 2*DINNER + DSTATE + c4);
        sCt[c4+0][r] = v.x; sCt[c4+1][r] = v.y;
        sCt[c4+2][r] = v.z; sCt[c4+3][r] = v.w;
    }
    const float* hs = g_hstart + (size_t)ci * (DSTATE*HEADDIM);
    for (int u = tid; u < 64*16; u += 256) {
        const int r  = u >> 4;
        const int c4 = (u & 15) * 4;
        *(float4*)&sHS[r][c4] = *(const float4*)(hs + r*HEADDIM + c4);
    }
    if (tid < 64) sPc[tid] = g_P[(size_t)ci*CHUNK + tid];
    __syncthreads();

    const int tx = tid & 15;
    const int ty = tid >> 4;
    const int t0 = ty * 4;
    const int p0 = tx * 4;

    float acc[4][4];
    #pragma unroll
    for (int i = 0; i < 4; i++)
        #pragma unroll
        for (int j = 0; j < 4; j++) acc[i][j] = 0.f;

    #pragma unroll 4
    for (int n = 0; n < 64; n++) {
        float4 cv = *(const float4*)&sCt[n][t0];
        float4 hv = *(const float4*)&sHS[n][p0];
        float ct[4] = {cv.x, cv.y, cv.z, cv.w};
        float hh[4] = {hv.x, hv.y, hv.z, hv.w};
        #pragma unroll
        for (int i = 0; i < 4; i++)
            #pragma unroll
            for (int j = 0; j < 4; j++)
                acc[i][j] = fmaf(ct[i], hh[j], acc[i][j]);
    }

    #pragma unroll
    for (int i = 0; i < 4; i++) {
        const size_t row = rowbase + t0 + i;
        const float P = sPc[t0 + i];
        float4 yp = *(const float4*)(g_y + row * (size_t)DINNER + h*64 + p0);
        float4 zv = *(const float4*)(g_proj + row * (size_t)DIP + h*64 + p0);
        float ov[4];
        ov[0] = (yp.x + P*acc[i][0]) * (zv.x / (1.f + expf(-zv.x)));
        ov[1] = (yp.y + P*acc[i][1]) * (zv.y / (1.f + expf(-zv.y)));
        ov[2] = (yp.z + P*acc[i][2]) * (zv.z / (1.f + expf(-zv.z)));
        ov[3] = (yp.w + P*acc[i][3]) * (zv.w / (1.f + expf(-zv.w)));
        const size_t yo = row * (size_t)DINNER + h*64 + p0;
        #pragma unroll
        for (int j = 0; j < 4; j++) {
            __nv_bfloat16 hv = __float2bfloat16(ov[j]);
            g_yhi[yo + j] = hv;
            g_ylo[yo + j] = __float2bfloat16(ov[j] - __bfloat162float(hv));
        }
    }
}

// ============================================================
// launch
// ============================================================
extern "C" void kernel_launch(void* const* d_in, const int* in_sizes, int n_in,
                              void* d_out, int out_size)
{
    const float* x       = (const float*)d_in[0];
    const float* W_in    = (const float*)d_in[1];
    const float* conv_w  = (const float*)d_in[2];
    const float* conv_b  = (const float*)d_in[3];
    const float* A_log   = (const float*)d_in[4];
    const float* dt_bias = (const float*)d_in[5];
    const float* W_out   = (const float*)d_in[6];
    float* out = (float*)d_out;

    float* proj; cudaGetSymbolAddress((void**)&proj, g_proj);
    __nv_bfloat16 *xhi, *xlo, *wihi, *wilo, *wohi, *wolo, *yhi, *ylo;
    cudaGetSymbolAddress((void**)&xhi,  g_xhi);
    cudaGetSymbolAddress((void**)&xlo,  g_xlo);
    cudaGetSymbolAddress((void**)&wihi, g_wihi);
    cudaGetSymbolAddress((void**)&wilo, g_wilo);
    cudaGetSymbolAddress((void**)&wohi, g_wohi);
    cudaGetSymbolAddress((void**)&wolo, g_wolo);
    cudaGetSymbolAddress((void**)&yhi,  g_yhi);
    cudaGetSymbolAddress((void**)&ylo,  g_ylo);

    cudaFuncSetAttribute(gemm_bf16x3_kernel,
                         cudaFuncAttributeMaxDynamicSharedMemorySize, GSMEM);

    // 0) split inputs / weights into bf16 hi/lo
    {
        int n1 = MROWS * DMODEL;
        split_bf16_kernel<<<(n1 + 255)/256, 256>>>(x, xhi, xlo, n1);
        int n2 = DIP * DMODEL;
        split_bf16_kernel<<<(n2 + 255)/256, 256>>>(W_in, wihi, wilo, n2);
        int n3 = DMODEL * DINNER;
        split_bf16_kernel<<<(n3 + 255)/256, 256>>>(W_out, wohi, wolo, n3);
    }
    // 1) in_proj (HMMA): proj = x @ W_in^T   M=4096, N=2192, K=512
    {
        dim3 grid((DIP + 63)/64, MROWS/128);
        gemm_bf16x3_kernel<<<grid, 256, GSMEM>>>(xhi, xlo, wihi, wilo,
                                                 proj, DIP, DMODEL);
    }
    // 2) conv + silu
    {
        int total = BATCH*SEQLEN*DINNER;
        conv_silu_kernel<<<(total + 255)/256, 256>>>(conv_w, conv_b);
    }
    // 3) dt -> dA
    {
        int total = BATCH*SEQLEN*NHEADS;
        dt_kernel<<<(total + 255)/256, 256>>>(A_log, dt_bias);
    }
    // 4a) per-chunk local scan
    {
        dim3 grid(4, NHEADS, BATCH*NCHUNK);
        scan_chunk_kernel<<<grid, 128>>>();
    }
    // 4b) carry propagation
    carry_kernel<<<BATCH*NHEADS, 256>>>();
    // 4c) correction + gate (writes y hi/lo bf16)
    correct_gate_kernel<<<NCI, 256>>>();
    // 5) out_proj (HMMA): out = y @ W_out^T  M=4096, N=512, K=1024
    {
        dim3 grid(DMODEL/64, MROWS/128);
        gemm_bf16x3_kernel<<<grid, 256, GSMEM>>>(yhi, ylo, wohi, wolo,
                                                 out, DMODEL, DINNER);
    }
}

// round 13
// speedup vs baseline: 1.8479x; 1.1987x over previous
#include <cuda_runtime.h>
#include <cuda_fp16.h>
#include <math.h>
#include <stdint.h>

// ---------------- problem constants ----------------
#define BATCH   2
#define SEQLEN  2048
#define DMODEL  512
#define DSTATE  64
#define DCONV   4
#define NHEADS  16
#define HEADDIM 64
#define DINNER  1024
#define DIP     2192                   // 2*DINNER + 2*DSTATE + NHEADS
#define MROWS   (BATCH*SEQLEN)         // 4096
#define CHUNK   64
#define NCHUNK  (SEQLEN/CHUNK)         // 32
#define NCI     (BATCH*NHEADS*NCHUNK)  // 1024
#define WSCALE     64.0f
#define WSCALE_INV 0.015625f

// ---------------- scratch ----------------
__device__ float g_proj  [(size_t)MROWS * DIP];
__device__ float g_y     [(size_t)MROWS * DINNER];
__device__ float g_P     [(size_t)NCI * CHUNK];
__device__ float g_vend  [(size_t)NCI * DSTATE * HEADDIM];
__device__ float g_hstart[(size_t)NCI * DSTATE * HEADDIM];

// fp16 tensors
__device__ __half g_xh [(size_t)MROWS * DMODEL];
__device__ __half g_wih[(size_t)DIP * DMODEL];
__device__ __half g_wil[(size_t)DIP * DMODEL];
__device__ __half g_woh[(size_t)DMODEL * DINNER];
__device__ __half g_wol[(size_t)DMODEL * DINNER];
__device__ __half g_yh [(size_t)MROWS * DINNER];

// ================= helpers =================
__device__ __forceinline__ uint32_t smem_u32(const void* p) {
    uint32_t a;
    asm("{ .reg .u64 t; cvta.to.shared.u64 t, %1; cvt.u32.u64 %0, t; }"
        : "=r"(a) : "l"(p));
    return a;
}

#define LDSM4(r, addr) \
    asm volatile("ldmatrix.sync.aligned.m8n8.x4.shared.b16 {%0,%1,%2,%3}, [%4];" \
        : "=r"((r)[0]), "=r"((r)[1]), "=r"((r)[2]), "=r"((r)[3]) : "r"(addr))

#define MMA_F16(c, a, b) \
    asm volatile("mma.sync.aligned.m16n8k16.row.col.f32.f16.f16.f32 " \
        "{%0,%1,%2,%3}, {%4,%5,%6,%7}, {%8,%9}, {%0,%1,%2,%3};" \
        : "+f"((c)[0]), "+f"((c)[1]), "+f"((c)[2]), "+f"((c)[3]) \
        : "r"((a)[0]), "r"((a)[1]), "r"((a)[2]), "r"((a)[3]), \
          "r"((b)[0]), "r"((b)[1]))

#define CP_ASYNC16(dst, src, sz) \
    asm volatile("cp.async.cg.shared.global [%0], [%1], 16, %2;" \
        :: "r"(dst), "l"(src), "r"(sz))
#define CP_COMMIT()  asm volatile("cp.async.commit_group;" ::: "memory")
#define CP_WAIT1()   asm volatile("cp.async.wait_group 1;" ::: "memory")
#define CP_WAIT0()   asm volatile("cp.async.wait_group 0;" ::: "memory")

// ============================================================
// weight split: fp32 -> (hi fp16, lo fp16), pre-scaled by WSCALE
// ============================================================
__global__ void split_h_kernel(const float* __restrict__ s,
                               __half* __restrict__ hi,
                               __half* __restrict__ lo, int n)
{
    int i = blockIdx.x * blockDim.x + threadIdx.x;
    if (i >= n) return;
    float v = s[i] * WSCALE;
    __half h = __float2half(v);
    hi[i] = h;
    lo[i] = __float2half(v - __half2float(h));
}

// activation cast: fp32 -> fp16
__global__ void cast_h_kernel(const float* __restrict__ s,
                              __half* __restrict__ d, int n)
{
    int i = blockIdx.x * blockDim.x + threadIdx.x;
    if (i < n) d[i] = __float2half(s[i]);
}

// ============================================================
// fp16 2-term GEMM via mma.sync, 3-stage cp.async, 2 CTAs/SM.
//   C[M,N] = (1/WSCALE) * A @ (Whi + Wlo)^T
// A:[M,K] fp16, Whi/Wlo:[N,K] fp16 row-major; C fp32 row-major ld=N.
// CTA 128x64, Kc=32, 256 threads (8 warps, 4x2), warp tile 32x32.
// 80B-padded smem rows. grid: (ceil(N/64), M/128). N guarded (zfill).
// ============================================================
#define ATILEB  10240      // 128 rows * 80B
#define BTILEB  5120       // 64 rows * 80B
#define STAGEB  20480      // A + Bhi + Blo
#define GSMEM   (STAGEB*3) // 61440

__global__ __launch_bounds__(256, 2)
void gemm_f16x2_kernel(const __half* __restrict__ A_g,
                       const __half* __restrict__ Bhi_g,
                       const __half* __restrict__ Blo_g,
                       float* __restrict__ C, int N, int K)
{
    extern __shared__ char dsm[];
    const uint32_t sb = smem_u32(dsm);
    const int tid  = threadIdx.x;
    const int wid  = tid >> 5;
    const int lane = tid & 31;
    const int wm   = wid & 3;
    const int wn   = wid >> 2;
    const int m0 = blockIdx.y * 128;
    const int n0 = blockIdx.x * 64;

    auto stage_load = [&](int kc, int buf) {
        const uint32_t sbb = sb + buf * STAGEB;
        #pragma unroll
        for (int i = 0; i < 4; i++) {
            const int u = tid + i * 256;
            uint32_t dst; const __half* src; int gr, row, seg, sz = 16;
            if (u < 512) {                 // A tile (128 rows)
                row = u >> 2; seg = u & 3;
                dst = sbb + row * 80 + seg * 16;
                src = A_g; gr = m0 + row;
            } else if (u < 768) {          // Bhi (64 rows)
                const int v = u - 512;
                row = v >> 2; seg = v & 3;
                dst = sbb + ATILEB + row * 80 + seg * 16;
                src = Bhi_g; gr = n0 + row;
                if (gr >= N) { gr = 0; sz = 0; }
            } else {                       // Blo (64 rows)
                const int v = u - 768;
                row = v >> 2; seg = v & 3;
                dst = sbb + ATILEB + BTILEB + row * 80 + seg * 16;
                src = Blo_g; gr = n0 + row;
                if (gr >= N) { gr = 0; sz = 0; }
            }
            CP_ASYNC16(dst, src + (size_t)gr * K + kc * 32 + seg * 8, sz);
        }
        CP_COMMIT();
    };

    float acc[2][4][4];
    #pragma unroll
    for (int mt = 0; mt < 2; mt++)
        #pragma unroll
        for (int nt = 0; nt < 4; nt++)
            #pragma unroll
            for (int q = 0; q < 4; q++) acc[mt][nt][q] = 0.f;

    const int nk = K >> 5;
    stage_load(0, 0);
    if (nk > 1) stage_load(1, 1);

    for (int kc = 0; kc < nk; kc++) {
        if (kc < nk - 1) CP_WAIT1(); else CP_WAIT0();
        __syncthreads();
        if (kc + 2 < nk) {
            int nb = kc + 2;
            stage_load(nb, nb - (nb / 3) * 3);
        }

        const uint32_t base = sb + (kc - (kc / 3) * 3) * STAGEB;

        #pragma unroll
        for (int ks = 0; ks < 2; ks++) {
            uint32_t ah[2][4];
            #pragma unroll
            for (int mt = 0; mt < 2; mt++) {
                const uint32_t ra = base
                    + (wm*32 + mt*16 + (lane & 15)) * 80
                    + ks*32 + ((lane >> 4) & 1) * 16;
                LDSM4(ah[mt], ra);
            }
            uint32_t bh[4][2], bl[4][2];
            #pragma unroll
            for (int np = 0; np < 2; np++) {
                const uint32_t rb = base + ATILEB
                    + (wn*32 + np*16 + ((lane >> 4) & 1) * 8 + (lane & 7)) * 80
                    + ks*32 + ((lane >> 3) & 1) * 16;
                uint32_t r4[4];
                LDSM4(r4, rb);
                bh[np*2][0] = r4[0]; bh[np*2][1] = r4[1];
                bh[np*2+1][0] = r4[2]; bh[np*2+1][1] = r4[3];
                LDSM4(r4, rb + BTILEB);
                bl[np*2][0] = r4[0]; bl[np*2][1] = r4[1];
                bl[np*2+1][0] = r4[2]; bl[np*2+1][1] = r4[3];
            }
            #pragma unroll
            for (int mt = 0; mt < 2; mt++)
                #pragma unroll
                for (int nt = 0; nt < 4; nt++) {
                    MMA_F16(acc[mt][nt], ah[mt], bh[nt]);
                    MMA_F16(acc[mt][nt], ah[mt], bl[nt]);
                }
        }
    }

    // ---- epilogue (undo WSCALE) ----
    #pragma unroll
    for (int mt = 0; mt < 2; mt++) {
        const int r0 = m0 + wm*32 + mt*16 + (lane >> 2);
        #pragma unroll
        for (int nt = 0; nt < 4; nt++) {
            const int cc = n0 + wn*32 + nt*8 + (lane & 3)*2;
            if (cc < N) {
                *(float2*)(C + (size_t)r0       * N + cc) =
                    make_float2(acc[mt][nt][0]*WSCALE_INV, acc[mt][nt][1]*WSCALE_INV);
                *(float2*)(C + (size_t)(r0 + 8) * N + cc) =
                    make_float2(acc[mt][nt][2]*WSCALE_INV, acc[mt][nt][3]*WSCALE_INV);
            }
        }
    }
}

// ============================================================
// Phase A: per-chunk local scan with FUSED conv+silu and dt->dA.
// grid (4 pg, NHEADS, BATCH*NCHUNK), 128 threads.
// ============================================================
__global__ __launch_bounds__(128, 1)
void scan_chunk_kernel(const float* __restrict__ cw,
                       const float* __restrict__ cb,
                       const float* __restrict__ A_log,
                       const float* __restrict__ dt_bias)
{
    const int pg = blockIdx.x;
    const int h  = blockIdx.y;
    const int bz = blockIdx.z;
    const int b  = bz >> 5;
    const int c  = bz & 31;

    const int tid  = threadIdx.x;
    const int lane = tid & 31;
    const int w    = tid >> 5;
    const int pi   = lane & 3;
    const int ng   = lane >> 2;
    const int p_local = w*4 + pi;
    const int n0   = ng * 8;

    __shared__ float sB [64][64];
    __shared__ float sC [64][64];
    __shared__ float sX [64][16];
    __shared__ float sXS[67][16];     // raw xs slice incl. 3-row halo
    __shared__ float sDA[64];
    __shared__ float sP [64];
    __shared__ float scw[64];
    __shared__ float scb[16];

    const size_t rowbase = (size_t)b * SEQLEN + (size_t)c * CHUNK;
    const int pcol = h*64 + pg*16;
    const size_t ci = ((size_t)(b*NHEADS + h) * NCHUNK + c);

    // stage B, C
    for (int u = tid; u < 64*16; u += 128) {
        const int r  = u >> 4;
        const int c4 = (u & 15) * 4;
        const float* src = g_proj + (rowbase + r) * (size_t)DIP;
        *(float4*)&sB[r][c4] = *(const float4*)(src + 2*DINNER + c4);
        *(float4*)&sC[r][c4] = *(const float4*)(src + 2*DINNER + DSTATE + c4);
    }
    // stage raw xs slice (rows tc-3 .. tc+63)
    for (int u = tid; u < 67*4; u += 128) {
        const int r  = u >> 2;
        const int c4 = (u & 3) * 4;
        float4 v = make_float4(0.f, 0.f, 0.f, 0.f);
        if (c > 0 || r >= 3)
            v = *(const float4*)(g_proj + (rowbase - 3 + r) * (size_t)DIP
                                 + DINNER + pcol + c4);
        *(float4*)&sXS[r][c4] = v;
    }
    // conv weights & bias for these 16 channels
    if (tid < 64) scw[tid] = cw[(pcol + (tid >> 2)) * 4 + (tid & 3)];
    if (tid < 16) scb[tid] = cb[pcol + tid];
    // dA from raw dt
    if (tid < 64) {
        float dtr = g_proj[(rowbase + tid) * (size_t)DIP
                           + 2*DINNER + 2*DSTATE + h] + dt_bias[h];
        float sp = (dtr > 20.f) ? dtr : log1pf(expf(dtr));
        float v  = expf(sp * (-expf(A_log[h])));
        sDA[tid] = v;
        sP[tid]  = v;
    }
    __syncthreads();

    // conv + silu -> sX
    for (int u = tid; u < 64*16; u += 128) {
        const int r = u >> 4;
        const int p = u & 15;
        float a = scb[p];
        a = fmaf(scw[p*4+0], sXS[r  ][p], a);
        a = fmaf(scw[p*4+1], sXS[r+1][p], a);
        a = fmaf(scw[p*4+2], sXS[r+2][p], a);
        a = fmaf(scw[p*4+3], sXS[r+3][p], a);
        sX[r][p] = a / (1.f + expf(-a));
    }

    // inclusive cumprod of dA (syncs also protect sX)
    #pragma unroll
    for (int off = 1; off < 64; off <<= 1) {
        float v = 0.f;
        if (tid < 64) {
            v = sP[tid];
            if (tid >= off) v *= sP[tid - off];
        }
        __syncthreads();
        if (tid < 64) sP[tid] = v;
        __syncthreads();
    }
    if (tid < 64 && pg == 0)
        g_P[ci*CHUNK + tid] = sP[tid];

    float s[8];
    #pragma unroll
    for (int j = 0; j < 8; j++) s[j] = 0.f;

    #pragma unroll 1
    for (int g = 0; g < 64; g += 8) {
        float acc[8];
        #pragma unroll
        for (int q = 0; q < 8; q++) {
            const int tt = g + q;
            const float da = sDA[tt];
            const float xv = sX[tt][p_local];
            float4 b0 = *(const float4*)&sB[tt][n0];
            float4 b1 = *(const float4*)&sB[tt][n0+4];
            float4 c0 = *(const float4*)&sC[tt][n0];
            float4 c1 = *(const float4*)&sC[tt][n0+4];
            s[0] = fmaf(da, s[0], b0.x * xv);
            s[1] = fmaf(da, s[1], b0.y * xv);
            s[2] = fmaf(da, s[2], b0.z * xv);
            s[3] = fmaf(da, s[3], b0.w * xv);
            s[4] = fmaf(da, s[4], b1.x * xv);
            s[5] = fmaf(da, s[5], b1.y * xv);
            s[6] = fmaf(da, s[6], b1.z * xv);
            s[7] = fmaf(da, s[7], b1.w * xv);
            float a0 = c0.x * s[0];
            float a1 = c0.y * s[1];
            a0 = fmaf(c0.z, s[2], a0);
            a1 = fmaf(c0.w, s[3], a1);
            a0 = fmaf(c1.x, s[4], a0);
            a1 = fmaf(c1.y, s[5], a1);
            a0 = fmaf(c1.z, s[6], a0);
            a1 = fmaf(c1.w, s[7], a1);
            acc[q] = a0 + a1;
        }
        #pragma unroll
        for (int q = 0; q < 8; q++) {
            float a = acc[q];
            a += __shfl_xor_sync(0xffffffffu, a, 4);
            a += __shfl_xor_sync(0xffffffffu, a, 8);
            a += __shfl_xor_sync(0xffffffffu, a, 16);
            acc[q] = a;
        }
        if (ng == 0) {
            #pragma unroll
            for (int q = 0; q < 8; q++) {
                g_y[(rowbase + g + q) * (size_t)DINNER + pcol + p_local] = acc[q];
            }
        }
    }

    float* vend = g_vend + ci * (size_t)(DSTATE*HEADDIM);
    #pragma unroll
    for (int j = 0; j < 8; j++)
        vend[(n0 + j) * HEADDIM + pg*16 + p_local] = s[j];
}

// ============================================================
// Phase B: carry propagation across chunks (prefetched).
// ============================================================
__global__ __launch_bounds__(256, 1)
void carry_kernel()
{
    const int bh  = blockIdx.x;
    const int tid = threadIdx.x;
    const size_t base = (size_t)bh * NCHUNK;

    float hreg[16], pre[16];
    #pragma unroll
    for (int k = 0; k < 16; k++) hreg[k] = 0.f;

    {
        const float* ve = g_vend + base * (size_t)(DSTATE*HEADDIM);
        #pragma unroll
        for (int k = 0; k < 16; k++) pre[k] = ve[tid + k*256];
    }
    float Pnext = g_P[base*CHUNK + (CHUNK-1)];

    for (int c = 0; c < NCHUNK; c++) {
        const size_t ci = base + c;
        const float Pend = Pnext;
        float* hs = g_hstart + ci * (size_t)(DSTATE*HEADDIM);

        float nxt[16];
        if (c + 1 < NCHUNK) {
            const float* ve2 = g_vend + (ci + 1) * (size_t)(DSTATE*HEADDIM);
            Pnext = g_P[(ci + 1)*CHUNK + (CHUNK-1)];
            #pragma unroll
            for (int k = 0; k < 16; k++) nxt[k] = ve2[tid + k*256];
        }
        #pragma unroll
        for (int k = 0; k < 16; k++) {
            hs[tid + k*256] = hreg[k];
            hreg[k] = fmaf(Pend, hreg[k], pre[k]);
        }
        #pragma unroll
        for (int k = 0; k < 16; k++) pre[k] = nxt[k];
    }
}

// ============================================================
// Phase C: correction + gate, writes y as fp16.
// ============================================================
__global__ __launch_bounds__(256, 4)
void correct_gate_kernel()
{
    const int ci = blockIdx.x;
    const int c  = ci & 31;
    const int bh = ci >> 5;
    const int h  = bh & 15;
    const int b  = bh >> 4;
    const int tid = threadIdx.x;

    __shared__ float sCt[64][72];
    __shared__ float sHS[64][64];
    __shared__ float sPc[64];

    const size_t rowbase = (size_t)b * SEQLEN + (size_t)c * CHUNK;

    for (int u = tid; u < 64*16; u += 256) {
        const int r  = u >> 4;
        const int c4 = (u & 15) * 4;
        float4 v = *(const float4*)(g_proj + (rowbase + r) * (size_t)DIP
                                    + 2*DINNER + DSTATE + c4);
        sCt[c4+0][r] = v.x; sCt[c4+1][r] = v.y;
        sCt[c4+2][r] = v.z; sCt[c4+3][r] = v.w;
    }
    const float* hs = g_hstart + (size_t)ci * (DSTATE*HEADDIM);
    for (int u = tid; u < 64*16; u += 256) {
        const int r  = u >> 4;
        const int c4 = (u & 15) * 4;
        *(float4*)&sHS[r][c4] = *(const float4*)(hs + r*HEADDIM + c4);
    }
    if (tid < 64) sPc[tid] = g_P[(size_t)ci*CHUNK + tid];
    __syncthreads();

    const int tx = tid & 15;
    const int ty = tid >> 4;
    const int t0 = ty * 4;
    const int p0 = tx * 4;

    float acc[4][4];
    #pragma unroll
    for (int i = 0; i < 4; i++)
        #pragma unroll
        for (int j = 0; j < 4; j++) acc[i][j] = 0.f;

    #pragma unroll 4
    for (int n = 0; n < 64; n++) {
        float4 cv = *(const float4*)&sCt[n][t0];
        float4 hv = *(const float4*)&sHS[n][p0];
        float ct[4] = {cv.x, cv.y, cv.z, cv.w};
        float hh[4] = {hv.x, hv.y, hv.z, hv.w};
        #pragma unroll
        for (int i = 0; i < 4; i++)
            #pragma unroll
            for (int j = 0; j < 4; j++)
                acc[i][j] = fmaf(ct[i], hh[j], acc[i][j]);
    }

    #pragma unroll
    for (int i = 0; i < 4; i++) {
        const size_t row = rowbase + t0 + i;
        const float P = sPc[t0 + i];
        float4 yp = *(const float4*)(g_y + row * (size_t)DINNER + h*64 + p0);
        float4 zv = *(const float4*)(g_proj + row * (size_t)DIP + h*64 + p0);
        float ov[4];
        ov[0] = (yp.x + P*acc[i][0]) * (zv.x / (1.f + expf(-zv.x)));
        ov[1] = (yp.y + P*acc[i][1]) * (zv.y / (1.f + expf(-zv.y)));
        ov[2] = (yp.z + P*acc[i][2]) * (zv.z / (1.f + expf(-zv.z)));
        ov[3] = (yp.w + P*acc[i][3]) * (zv.w / (1.f + expf(-zv.w)));
        const size_t yo = row * (size_t)DINNER + h*64 + p0;
        __half2* dst = (__half2*)(g_yh + yo);
        dst[0] = __floats2half2_rn(ov[0], ov[1]);
        dst[1] = __floats2half2_rn(ov[2], ov[3]);
    }
}

// ============================================================
// launch
// ============================================================
extern "C" void kernel_launch(void* const* d_in, const int* in_sizes, int n_in,
                              void* d_out, int out_size)
{
    const float* x       = (const float*)d_in[0];
    const float* W_in    = (const float*)d_in[1];
    const float* conv_w  = (const float*)d_in[2];
    const float* conv_b  = (const float*)d_in[3];
    const float* A_log   = (const float*)d_in[4];
    const float* dt_bias = (const float*)d_in[5];
    const float* W_out   = (const float*)d_in[6];
    float* out = (float*)d_out;

    float* proj; cudaGetSymbolAddress((void**)&proj, g_proj);
    __half *xh, *wih, *wil, *woh, *wol, *yh;
    cudaGetSymbolAddress((void**)&xh,  g_xh);
    cudaGetSymbolAddress((void**)&wih, g_wih);
    cudaGetSymbolAddress((void**)&wil, g_wil);
    cudaGetSymbolAddress((void**)&woh, g_woh);
    cudaGetSymbolAddress((void**)&wol, g_wol);
    cudaGetSymbolAddress((void**)&yh,  g_yh);

    cudaFuncSetAttribute(gemm_f16x2_kernel,
                         cudaFuncAttributeMaxDynamicSharedMemorySize, GSMEM);

    // 0) cast x, split weights (scaled)
    {
        int n1 = MROWS * DMODEL;
        cast_h_kernel<<<(n1 + 255)/256, 256>>>(x, xh, n1);
        int n2 = DIP * DMODEL;
        split_h_kernel<<<(n2 + 255)/256, 256>>>(W_in, wih, wil, n2);
        int n3 = DMODEL * DINNER;
        split_h_kernel<<<(n3 + 255)/256, 256>>>(W_out, woh, wol, n3);
    }
    // 1) in_proj: proj = x @ W_in^T   M=4096, N=2192, K=512
    {
        dim3 grid((DIP + 63)/64, MROWS/128);
        gemm_f16x2_kernel<<<grid, 256, GSMEM>>>(xh, wih, wil, proj, DIP, DMODEL);
    }
    // 2) fused scan (conv+silu+dt inside)
    {
        dim3 grid(4, NHEADS, BATCH*NCHUNK);
        scan_chunk_kernel<<<grid, 128>>>(conv_w, conv_b, A_log, dt_bias);
    }
    // 3) carry propagation
    carry_kernel<<<BATCH*NHEADS, 256>>>();
    // 4) correction + gate (writes y fp16)
    correct_gate_kernel<<<NCI, 256>>>();
    // 5) out_proj: out = y @ W_out^T  M=4096, N=512, K=1024
    {
        dim3 grid(DMODEL/64, MROWS/128);
        gemm_f16x2_kernel<<<grid, 256, GSMEM>>>(yh, woh, wol, out, DMODEL, DINNER);
    }
}

// round 16
// speedup vs baseline: 2.2953x; 1.2422x over previous
#include <cuda_runtime.h>
#include <cuda_fp16.h>
#include <math.h>
#include <stdint.h>

// ---------------- problem constants ----------------
#define BATCH   2
#define SEQLEN  2048
#define DMODEL  512
#define DSTATE  64
#define DCONV   4
#define NHEADS  16
#define HEADDIM 64
#define DINNER  1024
#define DIP     2192                   // 2*DINNER + 2*DSTATE + NHEADS
#define MROWS   (BATCH*SEQLEN)         // 4096
#define CHUNK   64
#define NCHUNK  (SEQLEN/CHUNK)         // 32
#define NCI     (BATCH*NHEADS*NCHUNK)  // 1024
#define WSCALE     64.0f
#define WSCALE_INV 0.015625f

// ---------------- scratch ----------------
__device__ float g_proj  [(size_t)MROWS * DIP];
__device__ float g_y     [(size_t)MROWS * DINNER];
__device__ float g_P     [(size_t)NCI * CHUNK];
__device__ float g_vend  [(size_t)NCI * DSTATE * HEADDIM];
__device__ float g_hstart[(size_t)NCI * DSTATE * HEADDIM];

// fp16 tensors
__device__ __half g_xh [(size_t)MROWS * DMODEL];
__device__ __half g_wih[(size_t)DIP * DMODEL];
__device__ __half g_wil[(size_t)DIP * DMODEL];
__device__ __half g_woh[(size_t)DMODEL * DINNER];
__device__ __half g_wol[(size_t)DMODEL * DINNER];
__device__ __half g_yh [(size_t)MROWS * DINNER];

// ================= helpers =================
__device__ __forceinline__ uint32_t smem_u32(const void* p) {
    uint32_t a;
    asm("{ .reg .u64 t; cvta.to.shared.u64 t, %1; cvt.u32.u64 %0, t; }"
        : "=r"(a) : "l"(p));
    return a;
}

#define LDSM4(r, addr) \
    asm volatile("ldmatrix.sync.aligned.m8n8.x4.shared.b16 {%0,%1,%2,%3}, [%4];" \
        : "=r"((r)[0]), "=r"((r)[1]), "=r"((r)[2]), "=r"((r)[3]) : "r"(addr))
#define LDSM4T(r, addr) \
    asm volatile("ldmatrix.sync.aligned.m8n8.x4.trans.shared.b16 {%0,%1,%2,%3}, [%4];" \
        : "=r"((r)[0]), "=r"((r)[1]), "=r"((r)[2]), "=r"((r)[3]) : "r"(addr))

#define MMA_F16(c, a, b) \
    asm volatile("mma.sync.aligned.m16n8k16.row.col.f32.f16.f16.f32 " \
        "{%0,%1,%2,%3}, {%4,%5,%6,%7}, {%8,%9}, {%0,%1,%2,%3};" \
        : "+f"((c)[0]), "+f"((c)[1]), "+f"((c)[2]), "+f"((c)[3]) \
        : "r"((a)[0]), "r"((a)[1]), "r"((a)[2]), "r"((a)[3]), \
          "r"((b)[0]), "r"((b)[1]))

#define CP_ASYNC16(dst, src, sz) \
    asm volatile("cp.async.cg.shared.global [%0], [%1], 16, %2;" \
        :: "r"(dst), "l"(src), "r"(sz))
#define CP_COMMIT()  asm volatile("cp.async.commit_group;" ::: "memory")
#define CP_WAIT1()   asm volatile("cp.async.wait_group 1;" ::: "memory")
#define CP_WAIT0()   asm volatile("cp.async.wait_group 0;" ::: "memory")

__device__ __forceinline__ void split_h(float v, __half* hi, __half* lo) {
    __half h = __float2half(v);
    *hi = h;
    *lo = __float2half(v - __half2float(h));
}

// ============================================================
// weight split / cast kernels
// ============================================================
__global__ void split_h_kernel(const float* __restrict__ s,
                               __half* __restrict__ hi,
                               __half* __restrict__ lo, int n)
{
    int i = blockIdx.x * blockDim.x + threadIdx.x;
    if (i >= n) return;
    float v = s[i] * WSCALE;
    __half h = __float2half(v);
    hi[i] = h;
    lo[i] = __float2half(v - __half2float(h));
}

__global__ void cast_h_kernel(const float* __restrict__ s,
                              __half* __restrict__ d, int n)
{
    int i = blockIdx.x * blockDim.x + threadIdx.x;
    if (i < n) d[i] = __float2half(s[i]);
}

// ============================================================
// fp16 2-term GEMM (unchanged from R13 best)
// ============================================================
#define ATILEB  10240
#define BTILEB  5120
#define STAGEB  20480
#define GSMEM   (STAGEB*3)

__global__ __launch_bounds__(256, 2)
void gemm_f16x2_kernel(const __half* __restrict__ A_g,
                       const __half* __restrict__ Bhi_g,
                       const __half* __restrict__ Blo_g,
                       float* __restrict__ C, int N, int K)
{
    extern __shared__ char dsm[];
    const uint32_t sb = smem_u32(dsm);
    const int tid  = threadIdx.x;
    const int wid  = tid >> 5;
    const int lane = tid & 31;
    const int wm   = wid & 3;
    const int wn   = wid >> 2;
    const int m0 = blockIdx.y * 128;
    const int n0 = blockIdx.x * 64;

    auto stage_load = [&](int kc, int buf) {
        const uint32_t sbb = sb + buf * STAGEB;
        #pragma unroll
        for (int i = 0; i < 4; i++) {
            const int u = tid + i * 256;
            uint32_t dst; const __half* src; int gr, row, seg, sz = 16;
            if (u < 512) {
                row = u >> 2; seg = u & 3;
                dst = sbb + row * 80 + seg * 16;
                src = A_g; gr = m0 + row;
            } else if (u < 768) {
                const int v = u - 512;
                row = v >> 2; seg = v & 3;
                dst = sbb + ATILEB + row * 80 + seg * 16;
                src = Bhi_g; gr = n0 + row;
                if (gr >= N) { gr = 0; sz = 0; }
            } else {
                const int v = u - 768;
                row = v >> 2; seg = v & 3;
                dst = sbb + ATILEB + BTILEB + row * 80 + seg * 16;
                src = Blo_g; gr = n0 + row;
                if (gr >= N) { gr = 0; sz = 0; }
            }
            CP_ASYNC16(dst, src + (size_t)gr * K + kc * 32 + seg * 8, sz);
        }
        CP_COMMIT();
    };

    float acc[2][4][4];
    #pragma unroll
    for (int mt = 0; mt < 2; mt++)
        #pragma unroll
        for (int nt = 0; nt < 4; nt++)
            #pragma unroll
            for (int q = 0; q < 4; q++) acc[mt][nt][q] = 0.f;

    const int nk = K >> 5;
    stage_load(0, 0);
    if (nk > 1) stage_load(1, 1);

    for (int kc = 0; kc < nk; kc++) {
        if (kc < nk - 1) CP_WAIT1(); else CP_WAIT0();
        __syncthreads();
        if (kc + 2 < nk) {
            int nb = kc + 2;
            stage_load(nb, nb - (nb / 3) * 3);
        }

        const uint32_t base = sb + (kc - (kc / 3) * 3) * STAGEB;

        #pragma unroll
        for (int ks = 0; ks < 2; ks++) {
            uint32_t ah[2][4];
            #pragma unroll
            for (int mt = 0; mt < 2; mt++) {
                const uint32_t ra = base
                    + (wm*32 + mt*16 + (lane & 15)) * 80
                    + ks*32 + ((lane >> 4) & 1) * 16;
                LDSM4(ah[mt], ra);
            }
            uint32_t bh[4][2], bl[4][2];
            #pragma unroll
            for (int np = 0; np < 2; np++) {
                const uint32_t rb = base + ATILEB
                    + (wn*32 + np*16 + ((lane >> 4) & 1) * 8 + (lane & 7)) * 80
                    + ks*32 + ((lane >> 3) & 1) * 16;
                uint32_t r4[4];
                LDSM4(r4, rb);
                bh[np*2][0] = r4[0]; bh[np*2][1] = r4[1];
                bh[np*2+1][0] = r4[2]; bh[np*2+1][1] = r4[3];
                LDSM4(r4, rb + BTILEB);
                bl[np*2][0] = r4[0]; bl[np*2][1] = r4[1];
                bl[np*2+1][0] = r4[2]; bl[np*2+1][1] = r4[3];
            }
            #pragma unroll
            for (int mt = 0; mt < 2; mt++)
                #pragma unroll
                for (int nt = 0; nt < 4; nt++) {
                    MMA_F16(acc[mt][nt], ah[mt], bh[nt]);
                    MMA_F16(acc[mt][nt], ah[mt], bl[nt]);
                }
        }
    }

    #pragma unroll
    for (int mt = 0; mt < 2; mt++) {
        const int r0 = m0 + wm*32 + mt*16 + (lane >> 2);
        #pragma unroll
        for (int nt = 0; nt < 4; nt++) {
            const int cc = n0 + wn*32 + nt*8 + (lane & 3)*2;
            if (cc < N) {
                *(float2*)(C + (size_t)r0       * N + cc) =
                    make_float2(acc[mt][nt][0]*WSCALE_INV, acc[mt][nt][1]*WSCALE_INV);
                *(float2*)(C + (size_t)(r0 + 8) * N + cc) =
                    make_float2(acc[mt][nt][2]*WSCALE_INV, acc[mt][nt][3]*WSCALE_INV);
            }
        }
    }
}

// ============================================================
// SSD scan: tensor-core chunked scan, fused conv+silu+dt.
// One block per (b,h,chunk). 256 threads (8 warps, 4x2 -> 64x64).
//   G = C B^T (fp16 hi/lo 3-term, fp32 acc)
//   M[t,s] = G * exp(L_t - L_s) * (s<=t)
//   Y = M X  -> g_y (fp32 partial)
//   vend = (B*exp(L63-L_s))^T X -> g_vend
//   g_P[t] = exp(L_t)
// ============================================================
#define LDH  72
#define LDBY 144
#define OCH 0
#define OCL 9216
#define OBH 18432
#define OBL 27648
#define OXH 36864
#define OXL 46080
#define OMH 55296
#define OML 64512
#define OLG 73728
#define OCW 73984
#define OCB 75008
#define SSDSMEM 75264

__global__ __launch_bounds__(256)
void ssd_scan_kernel(const float* __restrict__ cw,
                     const float* __restrict__ cb,
                     const float* __restrict__ A_log,
                     const float* __restrict__ dt_bias)
{
    extern __shared__ char SMB[];
    __half* Ch = (__half*)(SMB+OCH); __half* Cl = (__half*)(SMB+OCL);
    __half* Bh = (__half*)(SMB+OBH); __half* Bl = (__half*)(SMB+OBL);
    __half* Xh = (__half*)(SMB+OXH); __half* Xl = (__half*)(SMB+OXL);
    __half* Mh = (__half*)(SMB+OMH); __half* Ml = (__half*)(SMB+OML);
    float*  XS = (float*)(SMB+OMH);            // overlay: 67x68 fp32 (consumed before M)
    float*  Lg = (float*)(SMB+OLG);
    float*  scw_ = (float*)(SMB+OCW);
    float*  scb_ = (float*)(SMB+OCB);
    const uint32_t sb = smem_u32(SMB);

    const int tid = threadIdx.x, lane = tid & 31, wid = tid >> 5;
    const int wm = wid & 3, wn = wid >> 2;
    const int ci = blockIdx.x;
    const int c  = ci & 31, bh = ci >> 5, h = bh & 15, b = bh >> 4;
    const size_t rowbase = (size_t)b * SEQLEN + (size_t)c * CHUNK;
    const int pcol = h * 64;

    scw_[tid] = cw[(pcol + (tid >> 2)) * 4 + (tid & 3)];
    if (tid < 64) scb_[tid] = cb[pcol + tid];
    if (tid < 64) {
        float dtr = g_proj[(rowbase + tid) * (size_t)DIP
                           + 2*DINNER + 2*DSTATE + h] + dt_bias[h];
        float sp = (dtr > 20.f) ? dtr : log1pf(expf(dtr));
        Lg[tid] = sp * (-expf(A_log[h]));     // log dA
    }
    // stage B, C (fp32 -> hi/lo fp16)
    for (int u = tid; u < 64*16; u += 256) {
        const int r = u >> 4, c4 = (u & 15) * 4;
        const float* src = g_proj + (rowbase + r) * (size_t)DIP;
        float4 vb = *(const float4*)(src + 2*DINNER + c4);
        float4 vc = *(const float4*)(src + 2*DINNER + DSTATE + c4);
        const int ix = r * LDH + c4;
        split_h(vb.x, &Bh[ix+0], &Bl[ix+0]); split_h(vb.y, &Bh[ix+1], &Bl[ix+1]);
        split_h(vb.z, &Bh[ix+2], &Bl[ix+2]); split_h(vb.w, &Bh[ix+3], &Bl[ix+3]);
        split_h(vc.x, &Ch[ix+0], &Cl[ix+0]); split_h(vc.y, &Ch[ix+1], &Cl[ix+1]);
        split_h(vc.z, &Ch[ix+2], &Cl[ix+2]); split_h(vc.w, &Ch[ix+3], &Cl[ix+3]);
    }
    // stage raw xs (67 rows incl. halo) into overlay
    for (int u = tid; u < 67*16; u += 256) {
        const int r = u >> 4, c4 = (u & 15) * 4;
        float4 v = make_float4(0.f, 0.f, 0.f, 0.f);
        if (c > 0 || r >= 3)
            v = *(const float4*)(g_proj + (rowbase - 3 + r) * (size_t)DIP
                                 + DINNER + pcol + c4);
        *(float4*)&XS[r * 68 + c4] = v;
    }
    __syncthreads();
    // inclusive cumsum of log dA
    #pragma unroll
    for (int off = 1; off < 64; off <<= 1) {
        float v = 0.f;
        if (tid < 64) { v = Lg[tid]; if (tid >= off) v += Lg[tid - off]; }
        __syncthreads();
        if (tid < 64) Lg[tid] = v;
        __syncthreads();
    }
    if (tid < 64) g_P[(size_t)ci * CHUNK + tid] = expf(Lg[tid]);
    // conv + silu -> X (hi/lo)
    for (int u = tid; u < 4096; u += 256) {
        const int t = u >> 6, p = u & 63;
        float a = scb_[p];
        a = fmaf(scw_[p*4+0], XS[(t+0)*68 + p], a);
        a = fmaf(scw_[p*4+1], XS[(t+1)*68 + p], a);
        a = fmaf(scw_[p*4+2], XS[(t+2)*68 + p], a);
        a = fmaf(scw_[p*4+3], XS[(t+3)*68 + p], a);
        a = a / (1.f + expf(-a));
        split_h(a, &Xh[t*LDH + p], &Xl[t*LDH + p]);
    }
    __syncthreads();

    // ---- GEMM1: G = C @ B^T (3-term) ----
    float g[4][4];
    #pragma unroll
    for (int nt = 0; nt < 4; nt++)
        #pragma unroll
        for (int q = 0; q < 4; q++) g[nt][q] = 0.f;
    #pragma unroll
    for (int ks = 0; ks < 4; ks++) {
        uint32_t ch4[4], cl4[4];
        const uint32_t ra = sb + OCH + (wm*16 + (lane & 15)) * LDBY
                            + ks*32 + ((lane >> 4) & 1) * 16;
        LDSM4(ch4, ra);
        LDSM4(cl4, ra + (OCL - OCH));
        uint32_t bhf[4][2], blf[4][2], r4[4];
        #pragma unroll
        for (int np = 0; np < 2; np++) {
            const uint32_t rb = sb + OBH
                + (wn*32 + np*16 + ((lane >> 4) & 1)*8 + (lane & 7)) * LDBY
                + ks*32 + ((lane >> 3) & 1) * 16;
            LDSM4(r4, rb);
            bhf[np*2][0] = r4[0]; bhf[np*2][1] = r4[1];
            bhf[np*2+1][0] = r4[2]; bhf[np*2+1][1] = r4[3];
            LDSM4(r4, rb + (OBL - OBH));
            blf[np*2][0] = r4[0]; blf[np*2][1] = r4[1];
            blf[np*2+1][0] = r4[2]; blf[np*2+1][1] = r4[3];
        }
        #pragma unroll
        for (int nt = 0; nt < 4; nt++) {
            MMA_F16(g[nt], ch4, bhf[nt]);
            MMA_F16(g[nt], ch4, blf[nt]);
            MMA_F16(g[nt], cl4, bhf[nt]);
        }
    }
    // ---- mask + decay -> M (hi/lo) ----
    const int t0 = wm*16 + (lane >> 2);
    const float Lt0 = Lg[t0], Lt1 = Lg[t0 + 8];
    #pragma unroll
    for (int nt = 0; nt < 4; nt++) {
        const int s0 = wn*32 + nt*8 + (lane & 3)*2;
        const float Ls0 = Lg[s0], Ls1 = Lg[s0 + 1];
        float m00 = (s0     <= t0    ) ? g[nt][0] * expf(Lt0 - Ls0) : 0.f;
        float m01 = (s0 + 1 <= t0    ) ? g[nt][1] * expf(Lt0 - Ls1) : 0.f;
        float m10 = (s0     <= t0 + 8) ? g[nt][2] * expf(Lt1 - Ls0) : 0.f;
        float m11 = (s0 + 1 <= t0 + 8) ? g[nt][3] * expf(Lt1 - Ls1) : 0.f;
        split_h(m00, &Mh[t0*LDH + s0],     &Ml[t0*LDH + s0]);
        split_h(m01, &Mh[t0*LDH + s0 + 1], &Ml[t0*LDH + s0 + 1]);
        split_h(m10, &Mh[(t0+8)*LDH + s0],     &Ml[(t0+8)*LDH + s0]);
        split_h(m11, &Mh[(t0+8)*LDH + s0 + 1], &Ml[(t0+8)*LDH + s0 + 1]);
    }
    __syncthreads();
    // ---- weight B in place: wB[s][n] = B * exp(L63 - L_s) ----
    const float L63 = Lg[63];
    for (int u = tid; u < 4096; u += 256) {
        const int s = u >> 6, n = u & 63;
        const float w = expf(L63 - Lg[s]);
        const int ix = s*LDH + n;
        const float v = (__half2float(Bh[ix]) + __half2float(Bl[ix])) * w;
        split_h(v, &Bh[ix], &Bl[ix]);
    }
    __syncthreads();

    // ---- GEMM2: Y = M @ X  (A normal, B=X via trans) ----
    float y[4][4];
    #pragma unroll
    for (int nt = 0; nt < 4; nt++)
        #pragma unroll
        for (int q = 0; q < 4; q++) y[nt][q] = 0.f;
    #pragma unroll
    for (int ks = 0; ks < 4; ks++) {
        uint32_t mh4[4], ml4[4];
        const uint32_t ra = sb + OMH + (wm*16 + (lane & 15)) * LDBY
                            + ks*32 + ((lane >> 4) & 1) * 16;
        LDSM4(mh4, ra);
        LDSM4(ml4, ra + (OML - OMH));
        uint32_t xhf[4][2], xlf[4][2], r4[4];
        #pragma unroll
        for (int pb = 0; pb < 2; pb++) {
            const uint32_t rb = sb + OXH
                + (ks*16 + ((lane >> 4) & 1)*8 + (lane & 7)) * LDBY
                + (wn*32 + pb*16 + ((lane >> 3) & 1)*8) * 2;
            LDSM4T(r4, rb);
            xhf[pb*2][0] = r4[0]; xhf[pb*2][1] = r4[2];
            xhf[pb*2+1][0] = r4[1]; xhf[pb*2+1][1] = r4[3];
            LDSM4T(r4, rb + (OXL - OXH));
            xlf[pb*2][0] = r4[0]; xlf[pb*2][1] = r4[2];
            xlf[pb*2+1][0] = r4[1]; xlf[pb*2+1][1] = r4[3];
        }
        #pragma unroll
        for (int nt = 0; nt < 4; nt++) {
            MMA_F16(y[nt], mh4, xhf[nt]);
            MMA_F16(y[nt], mh4, xlf[nt]);
            MMA_F16(y[nt], ml4, xhf[nt]);
        }
    }
    #pragma unroll
    for (int nt = 0; nt < 4; nt++) {
        const int p0 = wn*32 + nt*8 + (lane & 3)*2;
        *(float2*)(g_y + (rowbase + t0) * (size_t)DINNER + pcol + p0) =
            make_float2(y[nt][0], y[nt][1]);
        *(float2*)(g_y + (rowbase + t0 + 8) * (size_t)DINNER + pcol + p0) =
            make_float2(y[nt][2], y[nt][3]);
    }

    // ---- GEMM3: vend = wB^T @ X  (A via trans, B=X via trans) ----
    float v4[4][4];
    #pragma unroll
    for (int nt = 0; nt < 4; nt++)
        #pragma unroll
        for (int q = 0; q < 4; q++) v4[nt][q] = 0.f;
    #pragma unroll
    for (int ks = 0; ks < 4; ks++) {
        uint32_t ah4[4], al4[4], r4[4];
        const uint32_t ra = sb + OBH
            + (ks*16 + ((lane >> 4) & 1)*8 + (lane & 7)) * LDBY
            + (wm*16 + ((lane >> 3) & 1)*8) * 2;
        LDSM4T(ah4, ra);
        LDSM4T(al4, ra + (OBL - OBH));
        uint32_t xhf[4][2], xlf[4][2];
        #pragma unroll
        for (int pb = 0; pb < 2; pb++) {
            const uint32_t rb = sb + OXH
                + (ks*16 + ((lane >> 4) & 1)*8 + (lane & 7)) * LDBY
                + (wn*32 + pb*16 + ((lane >> 3) & 1)*8) * 2;
            LDSM4T(r4, rb);
            xhf[pb*2][0] = r4[0]; xhf[pb*2][1] = r4[2];
            xhf[pb*2+1][0] = r4[1]; xhf[pb*2+1][1] = r4[3];
            LDSM4T(r4, rb + (OXL - OXH));
            xlf[pb*2][0] = r4[0]; xlf[pb*2][1] = r4[2];
            xlf[pb*2+1][0] = r4[1]; xlf[pb*2+1][1] = r4[3];
        }
        #pragma unroll
        for (int nt = 0; nt < 4; nt++) {
            MMA_F16(v4[nt], ah4, xhf[nt]);
            MMA_F16(v4[nt], ah4, xlf[nt]);
            MMA_F16(v4[nt], al4, xhf[nt]);
        }
    }
    float* vend = g_vend + (size_t)ci * (DSTATE*HEADDIM);
    #pragma unroll
    for (int nt = 0; nt < 4; nt++) {
        const int p0 = wn*32 + nt*8 + (lane & 3)*2;
        *(float2*)(vend + t0 * HEADDIM + p0)       = make_float2(v4[nt][0], v4[nt][1]);
        *(float2*)(vend + (t0 + 8) * HEADDIM + p0) = make_float2(v4[nt][2], v4[nt][3]);
    }
}

// ============================================================
// Phase B: carry propagation (prefetched).
// ============================================================
__global__ __launch_bounds__(256, 1)
void carry_kernel()
{
    const int bh  = blockIdx.x;
    const int tid = threadIdx.x;
    const size_t base = (size_t)bh * NCHUNK;

    float hreg[16], pre[16];
    #pragma unroll
    for (int k = 0; k < 16; k++) hreg[k] = 0.f;

    {
        const float* ve = g_vend + base * (size_t)(DSTATE*HEADDIM);
        #pragma unroll
        for (int k = 0; k < 16; k++) pre[k] = ve[tid + k*256];
    }
    float Pnext = g_P[base*CHUNK + (CHUNK-1)];

    for (int c = 0; c < NCHUNK; c++) {
        const size_t ci = base + c;
        const float Pend = Pnext;
        float* hs = g_hstart + ci * (size_t)(DSTATE*HEADDIM);

        float nxt[16];
        if (c + 1 < NCHUNK) {
            const float* ve2 = g_vend + (ci + 1) * (size_t)(DSTATE*HEADDIM);
            Pnext = g_P[(ci + 1)*CHUNK + (CHUNK-1)];
            #pragma unroll
            for (int k = 0; k < 16; k++) nxt[k] = ve2[tid + k*256];
        }
        #pragma unroll
        for (int k = 0; k < 16; k++) {
            hs[tid + k*256] = hreg[k];
            hreg[k] = fmaf(Pend, hreg[k], pre[k]);
        }
        #pragma unroll
        for (int k = 0; k < 16; k++) pre[k] = nxt[k];
    }
}

// ============================================================
// Phase C: correction + gate, writes y as fp16.
// ============================================================
__global__ __launch_bounds__(256, 4)
void correct_gate_kernel()
{
    const int ci = blockIdx.x;
    const int c  = ci & 31;
    const int bh = ci >> 5;
    const int h  = bh & 15;
    const int b  = bh >> 4;
    const int tid = threadIdx.x;

    __shared__ float sCt[64][72];
    __shared__ float sHS[64][64];
    __shared__ float sPc[64];

    const size_t rowbase = (size_t)b * SEQLEN + (size_t)c * CHUNK;

    for (int u = tid; u < 64*16; u += 256) {
        const int r  = u >> 4;
        const int c4 = (u & 15) * 4;
        float4 v = *(const float4*)(g_proj + (rowbase + r) * (size_t)DIP
                                    + 2*DINNER + DSTATE + c4);
        sCt[c4+0][r] = v.x; sCt[c4+1][r] = v.y;
        sCt[c4+2][r] = v.z; sCt[c4+3][r] = v.w;
    }
    const float* hs = g_hstart + (size_t)ci * (DSTATE*HEADDIM);
    for (int u = tid; u < 64*16; u += 256) {
        const int r  = u >> 4;
        const int c4 = (u & 15) * 4;
        *(float4*)&sHS[r][c4] = *(const float4*)(hs + r*HEADDIM + c4);
    }
    if (tid < 64) sPc[tid] = g_P[(size_t)ci*CHUNK + tid];
    __syncthreads();

    const int tx = tid & 15;
    const int ty = tid >> 4;
    const int t0 = ty * 4;
    const int p0 = tx * 4;

    float acc[4][4];
    #pragma unroll
    for (int i = 0; i < 4; i++)
        #pragma unroll
        for (int j = 0; j < 4; j++) acc[i][j] = 0.f;

    #pragma unroll 4
    for (int n = 0; n < 64; n++) {
        float4 cv = *(const float4*)&sCt[n][t0];
        float4 hv = *(const float4*)&sHS[n][p0];
        float ct[4] = {cv.x, cv.y, cv.z, cv.w};
        float hh[4] = {hv.x, hv.y, hv.z, hv.w};
        #pragma unroll
        for (int i = 0; i < 4; i++)
            #pragma unroll
            for (int j = 0; j < 4; j++)
                acc[i][j] = fmaf(ct[i], hh[j], acc[i][j]);
    }

    #pragma unroll
    for (int i = 0; i < 4; i++) {
        const size_t row = rowbase + t0 + i;
        const float P = sPc[t0 + i];
        float4 yp = *(const float4*)(g_y + row * (size_t)DINNER + h*64 + p0);
        float4 zv = *(const float4*)(g_proj + row * (size_t)DIP + h*64 + p0);
        float ov[4];
        ov[0] = (yp.x + P*acc[i][0]) * (zv.x / (1.f + expf(-zv.x)));
        ov[1] = (yp.y + P*acc[i][1]) * (zv.y / (1.f + expf(-zv.y)));
        ov[2] = (yp.z + P*acc[i][2]) * (zv.z / (1.f + expf(-zv.z)));
        ov[3] = (yp.w + P*acc[i][3]) * (zv.w / (1.f + expf(-zv.w)));
        const size_t yo = row * (size_t)DINNER + h*64 + p0;
        __half2* dst = (__half2*)(g_yh + yo);
        dst[0] = __floats2half2_rn(ov[0], ov[1]);
        dst[1] = __floats2half2_rn(ov[2], ov[3]);
    }
}

// ============================================================
// launch
// ============================================================
extern "C" void kernel_launch(void* const* d_in, const int* in_sizes, int n_in,
                              void* d_out, int out_size)
{
    const float* x       = (const float*)d_in[0];
    const float* W_in    = (const float*)d_in[1];
    const float* conv_w  = (const float*)d_in[2];
    const float* conv_b  = (const float*)d_in[3];
    const float* A_log   = (const float*)d_in[4];
    const float* dt_bias = (const float*)d_in[5];
    const float* W_out   = (const float*)d_in[6];
    float* out = (float*)d_out;

    float* proj; cudaGetSymbolAddress((void**)&proj, g_proj);
    __half *xh, *wih, *wil, *woh, *wol, *yh;
    cudaGetSymbolAddress((void**)&xh,  g_xh);
    cudaGetSymbolAddress((void**)&wih, g_wih);
    cudaGetSymbolAddress((void**)&wil, g_wil);
    cudaGetSymbolAddress((void**)&woh, g_woh);
    cudaGetSymbolAddress((void**)&wol, g_wol);
    cudaGetSymbolAddress((void**)&yh,  g_yh);

    cudaFuncSetAttribute(gemm_f16x2_kernel,
                         cudaFuncAttributeMaxDynamicSharedMemorySize, GSMEM);
    cudaFuncSetAttribute(ssd_scan_kernel,
                         cudaFuncAttributeMaxDynamicSharedMemorySize, SSDSMEM);

    // 0) cast x, split weights (scaled)
    {
        int n1 = MROWS * DMODEL;
        cast_h_kernel<<<(n1 + 255)/256, 256>>>(x, xh, n1);
        int n2 = DIP * DMODEL;
        split_h_kernel<<<(n2 + 255)/256, 256>>>(W_in, wih, wil, n2);
        int n3 = DMODEL * DINNER;
        split_h_kernel<<<(n3 + 255)/256, 256>>>(W_out, woh, wol, n3);
    }
    // 1) in_proj: proj = x @ W_in^T
    {
        dim3 grid((DIP + 63)/64, MROWS/128);
        gemm_f16x2_kernel<<<grid, 256, GSMEM>>>(xh, wih, wil, proj, DIP, DMODEL);
    }
    // 2) SSD scan (tensor cores; conv+silu+dt fused)
    ssd_scan_kernel<<<NCI, 256, SSDSMEM>>>(conv_w, conv_b, A_log, dt_bias);
    // 3) carry propagation
    carry_kernel<<<BATCH*NHEADS, 256>>>();
    // 4) correction + gate (writes y fp16)
    correct_gate_kernel<<<NCI, 256>>>();
    // 5) out_proj: out = y @ W_out^T
    {
        dim3 grid(DMODEL/64, MROWS/128);
        gemm_f16x2_kernel<<<grid, 256, GSMEM>>>(yh, woh, wol, out, DMODEL, DINNER);
    }
}

// round 17
// speedup vs baseline: 2.5587x; 1.1148x over previous
#include <cuda_runtime.h>
#include <cuda_fp16.h>
#include <math.h>
#include <stdint.h>

// ---------------- problem constants ----------------
#define BATCH   2
#define SEQLEN  2048
#define DMODEL  512
#define DSTATE  64
#define DCONV   4
#define NHEADS  16
#define HEADDIM 64
#define DINNER  1024
#define DIP     2192                   // 2*DINNER + 2*DSTATE + NHEADS
#define MROWS   (BATCH*SEQLEN)         // 4096
#define CHUNK   64
#define NCHUNK  (SEQLEN/CHUNK)         // 32
#define NCI     (BATCH*NHEADS*NCHUNK)  // 1024
#define WSCALE     64.0f
#define WSCALE_INV 0.015625f

// ---------------- scratch ----------------
__device__ float g_proj  [(size_t)MROWS * DIP];
__device__ float g_y     [(size_t)MROWS * DINNER];
__device__ float g_P     [(size_t)NCI * CHUNK];
__device__ float g_vend  [(size_t)NCI * DSTATE * HEADDIM];
__device__ float g_hstart[(size_t)NCI * DSTATE * HEADDIM];

// fp16 tensors
__device__ __half g_xh [(size_t)MROWS * DMODEL];
__device__ __half g_wih[(size_t)DIP * DMODEL];     // in_proj W hi only (NT=1)
__device__ __half g_woh[(size_t)DMODEL * DINNER];
__device__ __half g_wol[(size_t)DMODEL * DINNER];
__device__ __half g_yh [(size_t)MROWS * DINNER];

// ================= helpers =================
__device__ __forceinline__ uint32_t smem_u32(const void* p) {
    uint32_t a;
    asm("{ .reg .u64 t; cvta.to.shared.u64 t, %1; cvt.u32.u64 %0, t; }"
        : "=r"(a) : "l"(p));
    return a;
}

#define LDSM4(r, addr) \
    asm volatile("ldmatrix.sync.aligned.m8n8.x4.shared.b16 {%0,%1,%2,%3}, [%4];" \
        : "=r"((r)[0]), "=r"((r)[1]), "=r"((r)[2]), "=r"((r)[3]) : "r"(addr))
#define LDSM4T(r, addr) \
    asm volatile("ldmatrix.sync.aligned.m8n8.x4.trans.shared.b16 {%0,%1,%2,%3}, [%4];" \
        : "=r"((r)[0]), "=r"((r)[1]), "=r"((r)[2]), "=r"((r)[3]) : "r"(addr))

#define MMA_F16(c, a, b) \
    asm volatile("mma.sync.aligned.m16n8k16.row.col.f32.f16.f16.f32 " \
        "{%0,%1,%2,%3}, {%4,%5,%6,%7}, {%8,%9}, {%0,%1,%2,%3};" \
        : "+f"((c)[0]), "+f"((c)[1]), "+f"((c)[2]), "+f"((c)[3]) \
        : "r"((a)[0]), "r"((a)[1]), "r"((a)[2]), "r"((a)[3]), \
          "r"((b)[0]), "r"((b)[1]))

#define CP_ASYNC16(dst, src, sz) \
    asm volatile("cp.async.cg.shared.global [%0], [%1], 16, %2;" \
        :: "r"(dst), "l"(src), "r"(sz))
#define CP_COMMIT()  asm volatile("cp.async.commit_group;" ::: "memory")
#define CP_WAIT1()   asm volatile("cp.async.wait_group 1;" ::: "memory")
#define CP_WAIT0()   asm volatile("cp.async.wait_group 0;" ::: "memory")

__device__ __forceinline__ void split_h(float v, __half* hi, __half* lo) {
    __half h = __float2half(v);
    *hi = h;
    *lo = __float2half(v - __half2float(h));
}

// ============================================================
// fused prep: x cast | W_in cast (scaled) | W_out split (scaled)
// ============================================================
#define NPX (MROWS*DMODEL)     // 2097152
#define NPI (DIP*DMODEL)       // 1122304
#define NPO (DMODEL*DINNER)    // 524288
__global__ void prep_kernel(const float* __restrict__ x,
                            const float* __restrict__ W_in,
                            const float* __restrict__ W_out)
{
    int i = blockIdx.x * blockDim.x + threadIdx.x;
    if (i < NPX) {
        g_xh[i] = __float2half(x[i]);
    } else if (i < NPX + NPI) {
        int j = i - NPX;
        g_wih[j] = __float2half(W_in[j] * WSCALE);
    } else if (i < NPX + NPI + NPO) {
        int j = i - NPX - NPI;
        float v = W_out[j] * WSCALE;
        __half h = __float2half(v);
        g_woh[j] = h;
        g_wol[j] = __float2half(v - __half2float(h));
    }
}

// ============================================================
// fp16 GEMM via mma.sync, templated term count.
//   NT=1: C = (1/WSCALE) * A @ Bhi^T
//   NT=2: C = (1/WSCALE) * A @ (Bhi+Blo)^T
// CTA 128x64, Kc=32, 256 threads (8 warps, 4x2), warp tile 32x32.
// ============================================================
#define ATILEB  10240
#define BTILEB  5120

template<int NT>
__global__ __launch_bounds__(256, 2)
void gemm_f16_kernel(const __half* __restrict__ A_g,
                     const __half* __restrict__ Bhi_g,
                     const __half* __restrict__ Blo_g,
                     float* __restrict__ C, int N, int K)
{
    constexpr int STB = ATILEB + NT * BTILEB;
    extern __shared__ char dsm[];
    const uint32_t sb = smem_u32(dsm);
    const int tid  = threadIdx.x;
    const int wid  = tid >> 5;
    const int lane = tid & 31;
    const int wm   = wid & 3;
    const int wn   = wid >> 2;
    const int m0 = blockIdx.y * 128;
    const int n0 = blockIdx.x * 64;

    auto stage_load = [&](int kc, int buf) {
        const uint32_t sbb = sb + buf * STB;
        #pragma unroll
        for (int i = 0; i < (NT == 2 ? 4 : 3); i++) {
            const int u = tid + i * 256;
            uint32_t dst; const __half* src; int gr, row, seg, sz = 16;
            if (u < 512) {
                row = u >> 2; seg = u & 3;
                dst = sbb + row * 80 + seg * 16;
                src = A_g; gr = m0 + row;
            } else if (u < 768) {
                const int v = u - 512;
                row = v >> 2; seg = v & 3;
                dst = sbb + ATILEB + row * 80 + seg * 16;
                src = Bhi_g; gr = n0 + row;
                if (gr >= N) { gr = 0; sz = 0; }
            } else {
                const int v = u - 768;
                row = v >> 2; seg = v & 3;
                dst = sbb + ATILEB + BTILEB + row * 80 + seg * 16;
                src = Blo_g; gr = n0 + row;
                if (gr >= N) { gr = 0; sz = 0; }
            }
            CP_ASYNC16(dst, src + (size_t)gr * K + kc * 32 + seg * 8, sz);
        }
        CP_COMMIT();
    };

    float acc[2][4][4];
    #pragma unroll
    for (int mt = 0; mt < 2; mt++)
        #pragma unroll
        for (int nt = 0; nt < 4; nt++)
            #pragma unroll
            for (int q = 0; q < 4; q++) acc[mt][nt][q] = 0.f;

    const int nk = K >> 5;
    stage_load(0, 0);
    if (nk > 1) stage_load(1, 1);

    for (int kc = 0; kc < nk; kc++) {
        if (kc < nk - 1) CP_WAIT1(); else CP_WAIT0();
        __syncthreads();
        if (kc + 2 < nk) {
            int nb = kc + 2;
            stage_load(nb, nb - (nb / 3) * 3);
        }

        const uint32_t base = sb + (kc - (kc / 3) * 3) * STB;

        #pragma unroll
        for (int ks = 0; ks < 2; ks++) {
            uint32_t ah[2][4];
            #pragma unroll
            for (int mt = 0; mt < 2; mt++) {
                const uint32_t ra = base
                    + (wm*32 + mt*16 + (lane & 15)) * 80
                    + ks*32 + ((lane >> 4) & 1) * 16;
                LDSM4(ah[mt], ra);
            }
            uint32_t bh[4][2], bl[4][2];
            #pragma unroll
            for (int np = 0; np < 2; np++) {
                const uint32_t rb = base + ATILEB
                    + (wn*32 + np*16 + ((lane >> 4) & 1) * 8 + (lane & 7)) * 80
                    + ks*32 + ((lane >> 3) & 1) * 16;
                uint32_t r4[4];
                LDSM4(r4, rb);
                bh[np*2][0] = r4[0]; bh[np*2][1] = r4[1];
                bh[np*2+1][0] = r4[2]; bh[np*2+1][1] = r4[3];
                if (NT == 2) {
                    LDSM4(r4, rb + BTILEB);
                    bl[np*2][0] = r4[0]; bl[np*2][1] = r4[1];
                    bl[np*2+1][0] = r4[2]; bl[np*2+1][1] = r4[3];
                }
            }
            #pragma unroll
            for (int mt = 0; mt < 2; mt++)
                #pragma unroll
                for (int nt = 0; nt < 4; nt++) {
                    MMA_F16(acc[mt][nt], ah[mt], bh[nt]);
                    if (NT == 2) MMA_F16(acc[mt][nt], ah[mt], bl[nt]);
                }
        }
    }

    #pragma unroll
    for (int mt = 0; mt < 2; mt++) {
        const int r0 = m0 + wm*32 + mt*16 + (lane >> 2);
        #pragma unroll
        for (int nt = 0; nt < 4; nt++) {
            const int cc = n0 + wn*32 + nt*8 + (lane & 3)*2;
            if (cc < N) {
                *(float2*)(C + (size_t)r0       * N + cc) =
                    make_float2(acc[mt][nt][0]*WSCALE_INV, acc[mt][nt][1]*WSCALE_INV);
                *(float2*)(C + (size_t)(r0 + 8) * N + cc) =
                    make_float2(acc[mt][nt][2]*WSCALE_INV, acc[mt][nt][3]*WSCALE_INV);
            }
        }
    }
}

// ============================================================
// SSD scan (unchanged from R16 best)
// ============================================================
#define LDH  72
#define LDBY 144
#define OCH 0
#define OCL 9216
#define OBH 18432
#define OBL 27648
#define OXH 36864
#define OXL 46080
#define OMH 55296
#define OML 64512
#define OLG 73728
#define OCW 73984
#define OCB 75008
#define SSDSMEM 75264

__global__ __launch_bounds__(256)
void ssd_scan_kernel(const float* __restrict__ cw,
                     const float* __restrict__ cb,
                     const float* __restrict__ A_log,
                     const float* __restrict__ dt_bias)
{
    extern __shared__ char SMB[];
    __half* Ch = (__half*)(SMB+OCH); __half* Cl = (__half*)(SMB+OCL);
    __half* Bh = (__half*)(SMB+OBH); __half* Bl = (__half*)(SMB+OBL);
    __half* Xh = (__half*)(SMB+OXH); __half* Xl = (__half*)(SMB+OXL);
    __half* Mh = (__half*)(SMB+OMH); __half* Ml = (__half*)(SMB+OML);
    float*  XS = (float*)(SMB+OMH);
    float*  Lg = (float*)(SMB+OLG);
    float*  scw_ = (float*)(SMB+OCW);
    float*  scb_ = (float*)(SMB+OCB);
    const uint32_t sb = smem_u32(SMB);

    const int tid = threadIdx.x, lane = tid & 31, wid = tid >> 5;
    const int wm = wid & 3, wn = wid >> 2;
    const int ci = blockIdx.x;
    const int c  = ci & 31, bh = ci >> 5, h = bh & 15, b = bh >> 4;
    const size_t rowbase = (size_t)b * SEQLEN + (size_t)c * CHUNK;
    const int pcol = h * 64;

    scw_[tid] = cw[(pcol + (tid >> 2)) * 4 + (tid & 3)];
    if (tid < 64) scb_[tid] = cb[pcol + tid];
    if (tid < 64) {
        float dtr = g_proj[(rowbase + tid) * (size_t)DIP
                           + 2*DINNER + 2*DSTATE + h] + dt_bias[h];
        float sp = (dtr > 20.f) ? dtr : log1pf(expf(dtr));
        Lg[tid] = sp * (-expf(A_log[h]));
    }
    for (int u = tid; u < 64*16; u += 256) {
        const int r = u >> 4, c4 = (u & 15) * 4;
        const float* src = g_proj + (rowbase + r) * (size_t)DIP;
        float4 vb = *(const float4*)(src + 2*DINNER + c4);
        float4 vc = *(const float4*)(src + 2*DINNER + DSTATE + c4);
        const int ix = r * LDH + c4;
        split_h(vb.x, &Bh[ix+0], &Bl[ix+0]); split_h(vb.y, &Bh[ix+1], &Bl[ix+1]);
        split_h(vb.z, &Bh[ix+2], &Bl[ix+2]); split_h(vb.w, &Bh[ix+3], &Bl[ix+3]);
        split_h(vc.x, &Ch[ix+0], &Cl[ix+0]); split_h(vc.y, &Ch[ix+1], &Cl[ix+1]);
        split_h(vc.z, &Ch[ix+2], &Cl[ix+2]); split_h(vc.w, &Ch[ix+3], &Cl[ix+3]);
    }
    for (int u = tid; u < 67*16; u += 256) {
        const int r = u >> 4, c4 = (u & 15) * 4;
        float4 v = make_float4(0.f, 0.f, 0.f, 0.f);
        if (c > 0 || r >= 3)
            v = *(const float4*)(g_proj + (rowbase - 3 + r) * (size_t)DIP
                                 + DINNER + pcol + c4);
        *(float4*)&XS[r * 68 + c4] = v;
    }
    __syncthreads();
    #pragma unroll
    for (int off = 1; off < 64; off <<= 1) {
        float v = 0.f;
        if (tid < 64) { v = Lg[tid]; if (tid >= off) v += Lg[tid - off]; }
        __syncthreads();
        if (tid < 64) Lg[tid] = v;
        __syncthreads();
    }
    if (tid < 64) g_P[(size_t)ci * CHUNK + tid] = expf(Lg[tid]);
    for (int u = tid; u < 4096; u += 256) {
        const int t = u >> 6, p = u & 63;
        float a = scb_[p];
        a = fmaf(scw_[p*4+0], XS[(t+0)*68 + p], a);
        a = fmaf(scw_[p*4+1], XS[(t+1)*68 + p], a);
        a = fmaf(scw_[p*4+2], XS[(t+2)*68 + p], a);
        a = fmaf(scw_[p*4+3], XS[(t+3)*68 + p], a);
        a = a / (1.f + expf(-a));
        split_h(a, &Xh[t*LDH + p], &Xl[t*LDH + p]);
    }
    __syncthreads();

    float g[4][4];
    #pragma unroll
    for (int nt = 0; nt < 4; nt++)
        #pragma unroll
        for (int q = 0; q < 4; q++) g[nt][q] = 0.f;
    #pragma unroll
    for (int ks = 0; ks < 4; ks++) {
        uint32_t ch4[4], cl4[4];
        const uint32_t ra = sb + OCH + (wm*16 + (lane & 15)) * LDBY
                            + ks*32 + ((lane >> 4) & 1) * 16;
        LDSM4(ch4, ra);
        LDSM4(cl4, ra + (OCL - OCH));
        uint32_t bhf[4][2], blf[4][2], r4[4];
        #pragma unroll
        for (int np = 0; np < 2; np++) {
            const uint32_t rb = sb + OBH
                + (wn*32 + np*16 + ((lane >> 4) & 1)*8 + (lane & 7)) * LDBY
                + ks*32 + ((lane >> 3) & 1) * 16;
            LDSM4(r4, rb);
            bhf[np*2][0] = r4[0]; bhf[np*2][1] = r4[1];
            bhf[np*2+1][0] = r4[2]; bhf[np*2+1][1] = r4[3];
            LDSM4(r4, rb + (OBL - OBH));
            blf[np*2][0] = r4[0]; blf[np*2][1] = r4[1];
            blf[np*2+1][0] = r4[2]; blf[np*2+1][1] = r4[3];
        }
        #pragma unroll
        for (int nt = 0; nt < 4; nt++) {
            MMA_F16(g[nt], ch4, bhf[nt]);
            MMA_F16(g[nt], ch4, blf[nt]);
            MMA_F16(g[nt], cl4, bhf[nt]);
        }
    }
    const int t0 = wm*16 + (lane >> 2);
    const float Lt0 = Lg[t0], Lt1 = Lg[t0 + 8];
    #pragma unroll
    for (int nt = 0; nt < 4; nt++) {
        const int s0 = wn*32 + nt*8 + (lane & 3)*2;
        const float Ls0 = Lg[s0], Ls1 = Lg[s0 + 1];
        float m00 = (s0     <= t0    ) ? g[nt][0] * expf(Lt0 - Ls0) : 0.f;
        float m01 = (s0 + 1 <= t0    ) ? g[nt][1] * expf(Lt0 - Ls1) : 0.f;
        float m10 = (s0     <= t0 + 8) ? g[nt][2] * expf(Lt1 - Ls0) : 0.f;
        float m11 = (s0 + 1 <= t0 + 8) ? g[nt][3] * expf(Lt1 - Ls1) : 0.f;
        split_h(m00, &Mh[t0*LDH + s0],     &Ml[t0*LDH + s0]);
        split_h(m01, &Mh[t0*LDH + s0 + 1], &Ml[t0*LDH + s0 + 1]);
        split_h(m10, &Mh[(t0+8)*LDH + s0],     &Ml[(t0+8)*LDH + s0]);
        split_h(m11, &Mh[(t0+8)*LDH + s0 + 1], &Ml[(t0+8)*LDH + s0 + 1]);
    }
    __syncthreads();
    const float L63 = Lg[63];
    for (int u = tid; u < 4096; u += 256) {
        const int s = u >> 6, n = u & 63;
        const float w = expf(L63 - Lg[s]);
        const int ix = s*LDH + n;
        const float v = (__half2float(Bh[ix]) + __half2float(Bl[ix])) * w;
        split_h(v, &Bh[ix], &Bl[ix]);
    }
    __syncthreads();

    float y[4][4];
    #pragma unroll
    for (int nt = 0; nt < 4; nt++)
        #pragma unroll
        for (int q = 0; q < 4; q++) y[nt][q] = 0.f;
    #pragma unroll
    for (int ks = 0; ks < 4; ks++) {
        uint32_t mh4[4], ml4[4];
        const uint32_t ra = sb + OMH + (wm*16 + (lane & 15)) * LDBY
                            + ks*32 + ((lane >> 4) & 1) * 16;
        LDSM4(mh4, ra);
        LDSM4(ml4, ra + (OML - OMH));
        uint32_t xhf[4][2], xlf[4][2], r4[4];
        #pragma unroll
        for (int pb = 0; pb < 2; pb++) {
            const uint32_t rb = sb + OXH
                + (ks*16 + ((lane >> 4) & 1)*8 + (lane & 7)) * LDBY
                + (wn*32 + pb*16 + ((lane >> 3) & 1)*8) * 2;
            LDSM4T(r4, rb);
            xhf[pb*2][0] = r4[0]; xhf[pb*2][1] = r4[2];
            xhf[pb*2+1][0] = r4[1]; xhf[pb*2+1][1] = r4[3];
            LDSM4T(r4, rb + (OXL - OXH));
            xlf[pb*2][0] = r4[0]; xlf[pb*2][1] = r4[2];
            xlf[pb*2+1][0] = r4[1]; xlf[pb*2+1][1] = r4[3];
        }
        #pragma unroll
        for (int nt = 0; nt < 4; nt++) {
            MMA_F16(y[nt], mh4, xhf[nt]);
            MMA_F16(y[nt], mh4, xlf[nt]);
            MMA_F16(y[nt], ml4, xhf[nt]);
        }
    }
    #pragma unroll
    for (int nt = 0; nt < 4; nt++) {
        const int p0 = wn*32 + nt*8 + (lane & 3)*2;
        *(float2*)(g_y + (rowbase + t0) * (size_t)DINNER + pcol + p0) =
            make_float2(y[nt][0], y[nt][1]);
        *(float2*)(g_y + (rowbase + t0 + 8) * (size_t)DINNER + pcol + p0) =
            make_float2(y[nt][2], y[nt][3]);
    }

    float v4[4][4];
    #pragma unroll
    for (int nt = 0; nt < 4; nt++)
        #pragma unroll
        for (int q = 0; q < 4; q++) v4[nt][q] = 0.f;
    #pragma unroll
    for (int ks = 0; ks < 4; ks++) {
        uint32_t ah4[4], al4[4], r4[4];
        const uint32_t ra = sb + OBH
            + (ks*16 + ((lane >> 4) & 1)*8 + (lane & 7)) * LDBY
            + (wm*16 + ((lane >> 3) & 1)*8) * 2;
        LDSM4T(ah4, ra);
        LDSM4T(al4, ra + (OBL - OBH));
        uint32_t xhf[4][2], xlf[4][2];
        #pragma unroll
        for (int pb = 0; pb < 2; pb++) {
            const uint32_t rb = sb + OXH
                + (ks*16 + ((lane >> 4) & 1)*8 + (lane & 7)) * LDBY
                + (wn*32 + pb*16 + ((lane >> 3) & 1)*8) * 2;
            LDSM4T(r4, rb);
            xhf[pb*2][0] = r4[0]; xhf[pb*2][1] = r4[2];
            xhf[pb*2+1][0] = r4[1]; xhf[pb*2+1][1] = r4[3];
            LDSM4T(r4, rb + (OXL - OXH));
            xlf[pb*2][0] = r4[0]; xlf[pb*2][1] = r4[2];
            xlf[pb*2+1][0] = r4[1]; xlf[pb*2+1][1] = r4[3];
        }
        #pragma unroll
        for (int nt = 0; nt < 4; nt++) {
            MMA_F16(v4[nt], ah4, xhf[nt]);
            MMA_F16(v4[nt], ah4, xlf[nt]);
            MMA_F16(v4[nt], al4, xhf[nt]);
        }
    }
    float* vend = g_vend + (size_t)ci * (DSTATE*HEADDIM);
    #pragma unroll
    for (int nt = 0; nt < 4; nt++) {
        const int p0 = wn*32 + nt*8 + (lane & 3)*2;
        *(float2*)(vend + t0 * HEADDIM + p0)       = make_float2(v4[nt][0], v4[nt][1]);
        *(float2*)(vend + (t0 + 8) * HEADDIM + p0) = make_float2(v4[nt][2], v4[nt][3]);
    }
}

// ============================================================
// Phase B: carry propagation (prefetched).
// ============================================================
__global__ __launch_bounds__(256, 1)
void carry_kernel()
{
    const int bh  = blockIdx.x;
    const int tid = threadIdx.x;
    const size_t base = (size_t)bh * NCHUNK;

    float hreg[16], pre[16];
    #pragma unroll
    for (int k = 0; k < 16; k++) hreg[k] = 0.f;

    {
        const float* ve = g_vend + base * (size_t)(DSTATE*HEADDIM);
        #pragma unroll
        for (int k = 0; k < 16; k++) pre[k] = ve[tid + k*256];
    }
    float Pnext = g_P[base*CHUNK + (CHUNK-1)];

    for (int c = 0; c < NCHUNK; c++) {
        const size_t ci = base + c;
        const float Pend = Pnext;
        float* hs = g_hstart + ci * (size_t)(DSTATE*HEADDIM);

        float nxt[16];
        if (c + 1 < NCHUNK) {
            const float* ve2 = g_vend + (ci + 1) * (size_t)(DSTATE*HEADDIM);
            Pnext = g_P[(ci + 1)*CHUNK + (CHUNK-1)];
            #pragma unroll
            for (int k = 0; k < 16; k++) nxt[k] = ve2[tid + k*256];
        }
        #pragma unroll
        for (int k = 0; k < 16; k++) {
            hs[tid + k*256] = hreg[k];
            hreg[k] = fmaf(Pend, hreg[k], pre[k]);
        }
        #pragma unroll
        for (int k = 0; k < 16; k++) pre[k] = nxt[k];
    }
}

// ============================================================
// Phase C: correction + gate, writes y as fp16.
// ============================================================
__global__ __launch_bounds__(256, 4)
void correct_gate_kernel()
{
    const int ci = blockIdx.x;
    const int c  = ci & 31;
    const int bh = ci >> 5;
    const int h  = bh & 15;
    const int b  = bh >> 4;
    const int tid = threadIdx.x;

    __shared__ float sCt[64][72];
    __shared__ float sHS[64][64];
    __shared__ float sPc[64];

    const size_t rowbase = (size_t)b * SEQLEN + (size_t)c * CHUNK;

    for (int u = tid; u < 64*16; u += 256) {
        const int r  = u >> 4;
        const int c4 = (u & 15) * 4;
        float4 v = *(const float4*)(g_proj + (rowbase + r) * (size_t)DIP
                                    + 2*DINNER + DSTATE + c4);
        sCt[c4+0][r] = v.x; sCt[c4+1][r] = v.y;
        sCt[c4+2][r] = v.z; sCt[c4+3][r] = v.w;
    }
    const float* hs = g_hstart + (size_t)ci * (DSTATE*HEADDIM);
    for (int u = tid; u < 64*16; u += 256) {
        const int r  = u >> 4;
        const int c4 = (u & 15) * 4;
        *(float4*)&sHS[r][c4] = *(const float4*)(hs + r*HEADDIM + c4);
    }
    if (tid < 64) sPc[tid] = g_P[(size_t)ci*CHUNK + tid];
    __syncthreads();

    const int tx = tid & 15;
    const int ty = tid >> 4;
    const int t0 = ty * 4;
    const int p0 = tx * 4;

    float acc[4][4];
    #pragma unroll
    for (int i = 0; i < 4; i++)
        #pragma unroll
        for (int j = 0; j < 4; j++) acc[i][j] = 0.f;

    #pragma unroll 4
    for (int n = 0; n < 64; n++) {
        float4 cv = *(const float4*)&sCt[n][t0];
        float4 hv = *(const float4*)&sHS[n][p0];
        float ct[4] = {cv.x, cv.y, cv.z, cv.w};
        float hh[4] = {hv.x, hv.y, hv.z, hv.w};
        #pragma unroll
        for (int i = 0; i < 4; i++)
            #pragma unroll
            for (int j = 0; j < 4; j++)
                acc[i][j] = fmaf(ct[i], hh[j], acc[i][j]);
    }

    #pragma unroll
    for (int i = 0; i < 4; i++) {
        const size_t row = rowbase + t0 + i;
        const float P = sPc[t0 + i];
        float4 yp = *(const float4*)(g_y + row * (size_t)DINNER + h*64 + p0);
        float4 zv = *(const float4*)(g_proj + row * (size_t)DIP + h*64 + p0);
        float ov[4];
        ov[0] = (yp.x + P*acc[i][0]) * (zv.x / (1.f + expf(-zv.x)));
        ov[1] = (yp.y + P*acc[i][1]) * (zv.y / (1.f + expf(-zv.y)));
        ov[2] = (yp.z + P*acc[i][2]) * (zv.z / (1.f + expf(-zv.z)));
        ov[3] = (yp.w + P*acc[i][3]) * (zv.w / (1.f + expf(-zv.w)));
        const size_t yo = row * (size_t)DINNER + h*64 + p0;
        __half2* dst = (__half2*)(g_yh + yo);
        dst[0] = __floats2half2_rn(ov[0], ov[1]);
        dst[1] = __floats2half2_rn(ov[2], ov[3]);
    }
}

// ============================================================
// launch
// ============================================================
extern "C" void kernel_launch(void* const* d_in, const int* in_sizes, int n_in,
                              void* d_out, int out_size)
{
    const float* x       = (const float*)d_in[0];
    const float* W_in    = (const float*)d_in[1];
    const float* conv_w  = (const float*)d_in[2];
    const float* conv_b  = (const float*)d_in[3];
    const float* A_log   = (const float*)d_in[4];
    const float* dt_bias = (const float*)d_in[5];
    const float* W_out   = (const float*)d_in[6];
    float* out = (float*)d_out;

    float* proj; cudaGetSymbolAddress((void**)&proj, g_proj);
    __half *xh, *wih, *woh, *wol, *yh;
    cudaGetSymbolAddress((void**)&xh,  g_xh);
    cudaGetSymbolAddress((void**)&wih, g_wih);
    cudaGetSymbolAddress((void**)&woh, g_woh);
    cudaGetSymbolAddress((void**)&wol, g_wol);
    cudaGetSymbolAddress((void**)&yh,  g_yh);

    const int GS1 = (ATILEB + BTILEB) * 3;      // 46080
    const int GS2 = (ATILEB + 2*BTILEB) * 3;    // 61440
    cudaFuncSetAttribute(gemm_f16_kernel<1>,
                         cudaFuncAttributeMaxDynamicSharedMemorySize, GS1);
    cudaFuncSetAttribute(gemm_f16_kernel<2>,
                         cudaFuncAttributeMaxDynamicSharedMemorySize, GS2);
    cudaFuncSetAttribute(ssd_scan_kernel,
                         cudaFuncAttributeMaxDynamicSharedMemorySize, SSDSMEM);

    // 0) fused prep
    {
        int total = NPX + NPI + NPO;
        prep_kernel<<<(total + 255)/256, 256>>>(x, W_in, W_out);
    }
    // 1) in_proj (1-term fp16): proj = x @ W_in^T
    {
        dim3 grid((DIP + 63)/64, MROWS/128);
        gemm_f16_kernel<1><<<grid, 256, GS1>>>(xh, wih, nullptr, proj, DIP, DMODEL);
    }
    // 2) SSD scan (tensor cores; conv+silu+dt fused)
    ssd_scan_kernel<<<NCI, 256, SSDSMEM>>>(conv_w, conv_b, A_log, dt_bias);
    // 3) carry propagation
    carry_kernel<<<BATCH*NHEADS, 256>>>();
    // 4) correction + gate (writes y fp16)
    correct_gate_kernel<<<NCI, 256>>>();
    // 5) out_proj (2-term fp16, exact weights): out = y @ W_out^T
    {
        dim3 grid(DMODEL/64, MROWS/128);
        gemm_f16_kernel<2><<<grid, 256, GS2>>>(yh, woh, wol, out, DMODEL, DINNER);
    }
}